// round 15
// baseline (speedup 1.0000x reference)
#include <cuda_runtime.h>
#include <cuda_bf16.h>

// ---------------- problem constants ----------------
#define BATCH 32
#define DIM   7168
#define H     128
#define QLR   1536
#define KVLR  512
#define DN    128
#define DR    64
#define DV    128
#define QKD   192
#define MAXS  4096
#define QDIM  (H*QKD)      // 24576
#define KCAT  (KVLR+DR)    // 576
#define ODIM  (H*DV)       // 16384
#define NBLK  (MAXS/256)   // 16 t-blocks

#define SCALE_F 0.07216878364870322f
#define EPS_F   1e-6f

typedef unsigned long long ull;

// ---------------- helpers ----------------
__device__ __forceinline__ ull fma2(ull a, ull b, ull c) {
    ull d;
    asm("fma.rn.f32x2 %0, %1, %2, %3;" : "=l"(d) : "l"(a), "l"(b), "l"(c));
    return d;
}
__device__ __forceinline__ ull dup2(float x) {
    ull d;
    asm("mov.b64 %0, {%1, %1};" : "=l"(d) : "f"(x));
    return d;
}
__device__ __forceinline__ float2 u2f(ull v) {
    float2 f;
    f.x = __uint_as_float((unsigned)(v & 0xffffffffull));
    f.y = __uint_as_float((unsigned)(v >> 32));
    return f;
}
__device__ __forceinline__ unsigned f2tf(float f) {
    unsigned u; asm("cvt.rna.tf32.f32 %0, %1;" : "=r"(u) : "f"(f)); return u;
}
__device__ __forceinline__ unsigned s2u(const void* p) {
    unsigned a;
    asm("{ .reg .u64 t; cvta.to.shared.u64 t, %1; cvt.u32.u64 %0, t; }" : "=r"(a) : "l"(p));
    return a;
}
__device__ __forceinline__ void cpa16(unsigned dst, const void* src) {
    asm volatile("cp.async.cg.shared.global [%0], [%1], 16;" :: "r"(dst), "l"(src));
}
#define CPA_COMMIT() asm volatile("cp.async.commit_group;" ::: "memory")
#define CPA_WAIT1()  asm volatile("cp.async.wait_group 1;" ::: "memory")
__device__ __forceinline__ void mma8(float* c, const unsigned* a, const unsigned* b) {
    asm volatile("mma.sync.aligned.m16n8k8.row.col.f32.tf32.tf32.f32 "
                 "{%0,%1,%2,%3}, {%4,%5,%6,%7}, {%8,%9}, {%0,%1,%2,%3};"
                 : "+f"(c[0]), "+f"(c[1]), "+f"(c[2]), "+f"(c[3])
                 : "r"(a[0]), "r"(a[1]), "r"(a[2]), "r"(a[3]),
                   "r"(b[0]), "r"(b[1]));
}

// ---------------- scratch ----------------
__device__ __align__(16) float g_qlat  [BATCH * QLR];
__device__ __align__(16) float g_kvfull[BATCH * KCAT];
__device__ __align__(16) float g_kvnew [BATCH * KVLR];
__device__ __align__(16) float g_penew [BATCH * DR];
__device__ __align__(16) float g_q     [BATCH * QDIM];
__device__ __align__(16) float g_qcat  [BATCH * H * KCAT];
__device__ __align__(16) float g_scores[(long long)BATCH * H * MAXS];
__device__ __align__(16) float g_ml    [BATCH * H * NBLK * 2];
__device__ __align__(16) float g_w     [BATCH * H * NBLK];
__device__ __align__(16) float g_olat  [BATCH * H * KVLR];
__device__ __align__(16) float g_ohead [BATCH * ODIM];

// ---------------- reductions ----------------
__device__ __forceinline__ float warpSum(float v) {
#pragma unroll
    for (int o = 16; o; o >>= 1) v += __shfl_xor_sync(0xffffffffu, v, o);
    return v;
}
__device__ __forceinline__ float blockSum256(float v) {
    __shared__ float sm[8];
    int lane = threadIdx.x & 31, w = threadIdx.x >> 5;
    __syncthreads();
    v = warpSum(v);
    if (!lane) sm[w] = v;
    __syncthreads();
    float r = 0.f;
#pragma unroll
    for (int i = 0; i < 8; i++) r += sm[i];
    return r;
}

// =====================================================================
// TF32 MMA split-K GEMV v4: B via cp.async 3-stage ring
// [256 rows][16 fl] per stage; fragment LDS.128 at row*16+4tig
// (quad-k permutation; conflict-free). A staged in swizzled smem.
// smem: As 5120 + B 49152 = 54272 dynamic.
// =====================================================================
#define GV_SMEM (5120 + 49152)
__global__ void __launch_bounds__(256) gemv_mma(
    const float* __restrict__ A, const float* __restrict__ B, float* __restrict__ C,
    int lda, int ldb, int ldc, int kChunk)
{
    extern __shared__ char smraw[];
    unsigned (*As)[16][40] = (unsigned (*)[16][40])smraw;
    float* Bsf = (float*)(smraw + 5120);

    const int n0 = blockIdx.x * 256;
    const int ks = blockIdx.y * kChunk;
    const int nIter = kChunk / 16;

    const int tid = threadIdx.x, lane = tid & 31, wid = tid >> 5;
    const int gid = lane >> 2, tig = lane & 3;
    const int wn = wid * 32;

    const bool aon = tid < 128;
    const int am = tid >> 2, akq = (tid & 3) * 4;
    const int acol = am ^ (8 * ((akq >> 2) & 3));

    const float* bsrc = B + (long long)(n0 + tid) * ldb + ks;
    const unsigned bdst = s2u(Bsf) + tid * 64;

    // prologue: B stages 0,1 via cp.async; A buf0 via LDG+STS
#pragma unroll
    for (int st = 0; st < 2; st++) {
        if (st < nIter) {
            unsigned d = bdst + st * 16384;
            const float* s = bsrc + st * 16;
            cpa16(d, s);      cpa16(d+16, s+4);
            cpa16(d+32, s+8); cpa16(d+48, s+12);
        }
        CPA_COMMIT();
    }
    float4 ra = make_float4(0,0,0,0);
    if (aon) ra = *(const float4*)(A + (long long)am * lda + ks + akq);
    if (aon) {
        As[0][akq+0][acol] = f2tf(ra.x); As[0][akq+1][acol] = f2tf(ra.y);
        As[0][akq+2][acol] = f2tf(ra.z); As[0][akq+3][acol] = f2tf(ra.w);
    }

    float acc[2][4][4];
#pragma unroll
    for (int mi = 0; mi < 2; mi++)
#pragma unroll
        for (int nj = 0; nj < 4; nj++)
#pragma unroll
            for (int r = 0; r < 4; r++) acc[mi][nj][r] = 0.f;

    const int key = 8 * tig;

    for (int it = 0; it < nIter; it++) {
        const int cur = it & 1, nxt = cur ^ 1;
        const bool more = (it + 1) < nIter;
        if (more && aon)
            ra = *(const float4*)(A + (long long)am * lda + ks + (it+1)*16 + akq);

        CPA_WAIT1();
        __syncthreads();

        if (it + 2 < nIter) {
            unsigned d = bdst + ((it + 2) % 3) * 16384;
            const float* s = bsrc + (it + 2) * 16;
            cpa16(d, s);      cpa16(d+16, s+4);
            cpa16(d+32, s+8); cpa16(d+48, s+12);
        }
        CPA_COMMIT();

        const float* bst = Bsf + (it % 3) * 4096;
        unsigned bf[4][4];
#pragma unroll
        for (int nj = 0; nj < 4; nj++) {
            float4 f = *(const float4*)&bst[(wn + nj*8 + gid) * 16 + 4*tig];
            bf[nj][0] = f2tf(f.x); bf[nj][1] = f2tf(f.y);
            bf[nj][2] = f2tf(f.z); bf[nj][3] = f2tf(f.w);
        }
#pragma unroll
        for (int s = 0; s < 2; s++) {
            const int r0r = 4*tig + 2*s;
            unsigned af[2][4];
#pragma unroll
            for (int mi = 0; mi < 2; mi++) {
                int r0 = mi*16 + gid;
                af[mi][0] = As[cur][r0r  ][ r0    ^ key];
                af[mi][1] = As[cur][r0r  ][(r0+8) ^ key];
                af[mi][2] = As[cur][r0r+1][ r0    ^ key];
                af[mi][3] = As[cur][r0r+1][(r0+8) ^ key];
            }
#pragma unroll
            for (int mi = 0; mi < 2; mi++)
#pragma unroll
                for (int nj = 0; nj < 4; nj++)
                    mma8(acc[mi][nj], af[mi], &bf[nj][2*s]);
        }
        if (more && aon) {
            As[nxt][akq+0][acol] = f2tf(ra.x); As[nxt][akq+1][acol] = f2tf(ra.y);
            As[nxt][akq+2][acol] = f2tf(ra.z); As[nxt][akq+3][acol] = f2tf(ra.w);
        }
    }

#pragma unroll
    for (int mi = 0; mi < 2; mi++)
#pragma unroll
        for (int nj = 0; nj < 4; nj++) {
            float* cp = C + (long long)(mi*16+gid)*ldc + n0 + wn + nj*8 + 2*tig;
            atomicAdd(cp,           acc[mi][nj][0]);
            atomicAdd(cp + 1,       acc[mi][nj][1]);
            atomicAdd(cp + 8*ldc,   acc[mi][nj][2]);
            atomicAdd(cp + 8*ldc+1, acc[mi][nj][3]);
        }
}

// ---------------- merged norms ----------------
__global__ void __launch_bounds__(256) norms_kernel(
    float* __restrict__ qlat, const float* __restrict__ q_norm_w,
    const float* __restrict__ kvfull, const float* __restrict__ kv_norm,
    const float* __restrict__ fc, const float* __restrict__ fs,
    float* __restrict__ kvnew, float* __restrict__ penew)
{
    if (blockIdx.x < 32) {
        int b = blockIdx.x;
        float* row = qlat + (long long)b * QLR;
        float ss = 0.f;
        for (int i = threadIdx.x; i < QLR; i += 256) { float x = row[i]; ss += x * x; }
        ss = blockSum256(ss);
        __shared__ float s_scale;
        if (threadIdx.x == 0) s_scale = rsqrtf(ss / (float)QLR + EPS_F);
        __syncthreads();
        float sc = s_scale;
        for (int i = threadIdx.x; i < QLR; i += 256) row[i] = row[i] * sc * q_norm_w[i];
    } else {
        int b = blockIdx.x - 32;
        const float* row = kvfull + (long long)b * KCAT;
        float ss = 0.f;
        for (int i = threadIdx.x; i < KVLR; i += 256) { float x = row[i]; ss += x * x; }
        ss = blockSum256(ss);
        __shared__ float s_scale;
        if (threadIdx.x == 0) s_scale = rsqrtf(ss / (float)KVLR + EPS_F);
        __syncthreads();
        float sc = s_scale;
        for (int i = threadIdx.x; i < KVLR; i += 256)
            kvnew[(long long)b * KVLR + i] = row[i] * sc * kv_norm[i];
        if (threadIdx.x < 32) {
            int i = threadIdx.x;
            float x1 = row[KVLR + 2 * i], x2 = row[KVLR + 2 * i + 1];
            float c = fc[i], s = fs[i];
            penew[(long long)b * DR + 2 * i]     = x1 * c - x2 * s;
            penew[(long long)b * DR + 2 * i + 1] = x1 * s + x2 * c;
        }
    }
}

// ---------------- q rope -> qcat tail (scaled) ----------------
__global__ void __launch_bounds__(256) qrope_kernel(
    const float* __restrict__ q, const float* __restrict__ fc,
    const float* __restrict__ fs, float* __restrict__ qcat)
{
    int idx = blockIdx.x * 256 + threadIdx.x;
    if (idx >= BATCH * H * (DR / 2)) return;
    int i  = idx & 31;
    int bh = idx >> 5;
    int b  = bh >> 7, h = bh & 127;
    const float* src = q + (long long)b * QDIM + h * QKD + DN;
    float x1 = src[2 * i], x2 = src[2 * i + 1];
    float c = fc[i], s = fs[i];
    qcat[(long long)bh * KCAT + KVLR + 2 * i]     = (x1 * c - x2 * s) * SCALE_F;
    qcat[(long long)bh * KCAT + KVLR + 2 * i + 1] = (x1 * s + x2 * c) * SCALE_F;
}

// ---------------- q_abs (FFMA), 256 blocks ----------------
__global__ void __launch_bounds__(256) qabs_kernel(
    const float* __restrict__ q, const float* __restrict__ wkvb, float* __restrict__ qcat)
{
    int h = blockIdx.x >> 1;
    int c = (blockIdx.x & 1) * 256 + threadIdx.x;
    __shared__ __align__(16) float sq[DN][BATCH];
    int tid = threadIdx.x;
#pragma unroll
    for (int i = 0; i < 16; i++) {
        int idx = tid + i * 256;
        int d = idx >> 5, b = idx & 31;
        sq[d][b] = q[(long long)b * QDIM + h * QKD + d];
    }
    __syncthreads();
    ull acc[16];
#pragma unroll
    for (int i = 0; i < 16; i++) acc[i] = 0ull;
    const float* w = wkvb + (long long)h * 256 * KVLR + c;
#pragma unroll 4
    for (int d = 0; d < DN; d++) {
        ull w2 = dup2(w[(long long)d * KVLR]);
#pragma unroll
        for (int bp = 0; bp < 16; bp++) {
            ull qp = *(const ull*)&sq[d][bp * 2];
            acc[bp] = fma2(qp, w2, acc[bp]);
        }
    }
#pragma unroll
    for (int bp = 0; bp < 16; bp++) {
        float2 f = u2f(acc[bp]);
        qcat[((long long)(2 * bp + 0) * H + h) * KCAT + c] = f.x * SCALE_F;
        qcat[((long long)(2 * bp + 1) * H + h) * KCAT + c] = f.y * SCALE_F;
    }
}

// =====================================================================
// scores + block-local softmax, cp.async 3-stage B ring (R14 proven)
// =====================================================================
#define SC_SMEM 71680
__global__ void __launch_bounds__(256) scores_sm(
    const float* __restrict__ qcat, const float* __restrict__ kvc, const float* __restrict__ pec,
    const float* __restrict__ kvnew, const float* __restrict__ penew,
    float* __restrict__ S, float2* __restrict__ mlv, const int* __restrict__ spos_p)
{
    extern __shared__ char smraw[];
    unsigned (*As)[16][72] = (unsigned (*)[16][72])(smraw);
    float* Bsf            = (float*)(smraw + 9216);
    float (*red)[4]       = (float (*)[4])(smraw + 9216 + 61440);

    const int b = blockIdx.z, spos = *spos_p;
    const int t0 = blockIdx.x * 256, h0 = blockIdx.y * 64;
    const float* A = qcat + ((long long)b * H + h0) * KCAT;
    float* C = S + ((long long)b * H + h0) * MAXS;

    const int tid = threadIdx.x, lane = tid & 31, wid = tid >> 5;
    const int gid = lane >> 2, tig = lane & 3;
    const int wh = (wid & 1) * 32, wt = (wid >> 1) * 64;
    const int wtq = wid >> 1;

    const int ah = tid >> 2, akq = (tid & 3) * 4;
    const int acol = ah ^ (8 * ((akq >> 2) & 3));

    const int bt = t0 + tid;
    const float* kvsrc = (bt == spos) ? (kvnew + (long long)b * KVLR)
                                      : (kvc + ((long long)b * MAXS + bt) * KVLR);
    const float* pesrc = (bt == spos) ? (penew + (long long)b * DR)
                                      : (pec + ((long long)b * MAXS + bt) * DR);
    const unsigned browu = s2u(Bsf) + tid * 80;

    {
        unsigned d0 = browu;
        cpa16(d0, kvsrc);      cpa16(d0+16, kvsrc+4);
        cpa16(d0+32, kvsrc+8); cpa16(d0+48, kvsrc+12);
        CPA_COMMIT();
        unsigned d1 = browu + 20480;
        const float* s1 = kvsrc + 16;
        cpa16(d1, s1);      cpa16(d1+16, s1+4);
        cpa16(d1+32, s1+8); cpa16(d1+48, s1+12);
        CPA_COMMIT();
    }
    float4 ra = *(const float4*)(A + (long long)ah * KCAT + akq);
    As[0][akq+0][acol] = f2tf(ra.x); As[0][akq+1][acol] = f2tf(ra.y);
    As[0][akq+2][acol] = f2tf(ra.z); As[0][akq+3][acol] = f2tf(ra.w);

    float acc[2][8][4];
#pragma unroll
    for (int mi = 0; mi < 2; mi++)
#pragma unroll
        for (int nj = 0; nj < 8; nj++)
#pragma unroll
            for (int r = 0; r < 4; r++) acc[mi][nj][r] = 0.f;

    for (int it = 0; it < KCAT / 16; it++) {
        const int cur = it & 1, nxt = cur ^ 1;
        const bool more = (it + 1) < KCAT / 16;
        if (more)
            ra = *(const float4*)(A + (long long)ah * KCAT + (it+1)*16 + akq);

        CPA_WAIT1();
        __syncthreads();

        if (it + 2 < KCAT / 16) {
            const int k0 = (it + 2) * 16;
            const float* src = (k0 < KVLR) ? (kvsrc + k0) : (pesrc + (k0 - KVLR));
            unsigned dst = browu + ((it + 2) % 3) * 20480;
            cpa16(dst, src);      cpa16(dst+16, src+4);
            cpa16(dst+32, src+8); cpa16(dst+48, src+12);
        }
        CPA_COMMIT();

        const float* bst = Bsf + (it % 3) * 5120;
#pragma unroll
        for (int s = 0; s < 2; s++) {
            const int kk = s * 8;
            const int key0 = 8 * ((kk >> 2) & 3);
            const int key1 = 8 * (((kk >> 2) + 1) & 3);
            unsigned af[2][4];
#pragma unroll
            for (int mi = 0; mi < 2; mi++) {
                int r0 = wh + mi*16 + gid;
                af[mi][0] = As[cur][kk+tig  ][ r0    ^ key0];
                af[mi][1] = As[cur][kk+tig  ][(r0+8) ^ key0];
                af[mi][2] = As[cur][kk+tig+4][ r0    ^ key1];
                af[mi][3] = As[cur][kk+tig+4][(r0+8) ^ key1];
            }
            unsigned bf[8][2];
#pragma unroll
            for (int nj = 0; nj < 8; nj++) {
                int row = (wt + nj*8 + gid) * 20;
                bf[nj][0] = f2tf(bst[row + kk + tig]);
                bf[nj][1] = f2tf(bst[row + kk + tig + 4]);
            }
#pragma unroll
            for (int mi = 0; mi < 2; mi++)
#pragma unroll
                for (int nj = 0; nj < 8; nj++)
                    mma8(acc[mi][nj], af[mi], bf[nj]);
        }
        if (more) {
            As[nxt][akq+0][acol] = f2tf(ra.x); As[nxt][akq+1][acol] = f2tf(ra.y);
            As[nxt][akq+2][acol] = f2tf(ra.z); As[nxt][akq+3][acol] = f2tf(ra.w);
        }
    }

    // ---------------- block-local softmax epilogue ----------------
    float m_lo[2], m_hi[2];
#pragma unroll
    for (int mi = 0; mi < 2; mi++) {
        float a = -1e30f, c = -1e30f;
#pragma unroll
        for (int nj = 0; nj < 8; nj++) {
            int t = t0 + wt + nj*8 + 2*tig;
            float v0 = (t     <= spos) ? acc[mi][nj][0] : -1e30f;
            float v1 = (t + 1 <= spos) ? acc[mi][nj][1] : -1e30f;
            float v2 = (t     <= spos) ? acc[mi][nj][2] : -1e30f;
            float v3 = (t + 1 <= spos) ? acc[mi][nj][3] : -1e30f;
            a = fmaxf(a, fmaxf(v0, v1));
            c = fmaxf(c, fmaxf(v2, v3));
        }
        a = fmaxf(a, __shfl_xor_sync(0xffffffffu, a, 1));
        a = fmaxf(a, __shfl_xor_sync(0xffffffffu, a, 2));
        c = fmaxf(c, __shfl_xor_sync(0xffffffffu, c, 1));
        c = fmaxf(c, __shfl_xor_sync(0xffffffffu, c, 2));
        m_lo[mi] = a; m_hi[mi] = c;
    }
    __syncthreads();
    if (tig == 0) {
#pragma unroll
        for (int mi = 0; mi < 2; mi++) {
            red[wh + mi*16 + gid    ][wtq] = m_lo[mi];
            red[wh + mi*16 + gid + 8][wtq] = m_hi[mi];
        }
    }
    __syncthreads();
#pragma unroll
    for (int mi = 0; mi < 2; mi++) {
        int r = wh + mi*16 + gid;
        m_lo[mi] = fmaxf(fmaxf(red[r][0],   red[r][1]),   fmaxf(red[r][2],   red[r][3]));
        m_hi[mi] = fmaxf(fmaxf(red[r+8][0], red[r+8][1]), fmaxf(red[r+8][2], red[r+8][3]));
    }
    __syncthreads();
    float s_lo[2] = {0.f, 0.f}, s_hi[2] = {0.f, 0.f};
#pragma unroll
    for (int mi = 0; mi < 2; mi++) {
#pragma unroll
        for (int nj = 0; nj < 8; nj++) {
            int t = t0 + wt + nj*8 + 2*tig;
            float e0 = (t     <= spos) ? __expf(acc[mi][nj][0] - m_lo[mi]) : 0.f;
            float e1 = (t + 1 <= spos) ? __expf(acc[mi][nj][1] - m_lo[mi]) : 0.f;
            float e2 = (t     <= spos) ? __expf(acc[mi][nj][2] - m_hi[mi]) : 0.f;
            float e3 = (t + 1 <= spos) ? __expf(acc[mi][nj][3] - m_hi[mi]) : 0.f;
            acc[mi][nj][0] = e0; acc[mi][nj][1] = e1;
            acc[mi][nj][2] = e2; acc[mi][nj][3] = e3;
            s_lo[mi] += e0 + e1; s_hi[mi] += e2 + e3;
        }
        s_lo[mi] += __shfl_xor_sync(0xffffffffu, s_lo[mi], 1);
        s_lo[mi] += __shfl_xor_sync(0xffffffffu, s_lo[mi], 2);
        s_hi[mi] += __shfl_xor_sync(0xffffffffu, s_hi[mi], 1);
        s_hi[mi] += __shfl_xor_sync(0xffffffffu, s_hi[mi], 2);
    }
    if (tig == 0) {
#pragma unroll
        for (int mi = 0; mi < 2; mi++) {
            red[wh + mi*16 + gid    ][wtq] = s_lo[mi];
            red[wh + mi*16 + gid + 8][wtq] = s_hi[mi];
        }
    }
    __syncthreads();
    if (wtq == 0 && tig == 0) {
#pragma unroll
        for (int mi = 0; mi < 2; mi++) {
            int r = wh + mi*16 + gid;
            float l0 = red[r][0]   + red[r][1]   + red[r][2]   + red[r][3];
            float l1 = red[r+8][0] + red[r+8][1] + red[r+8][2] + red[r+8][3];
            mlv[((long long)(b * H + h0 + r))     * NBLK + blockIdx.x] = make_float2(m_lo[mi], l0);
            mlv[((long long)(b * H + h0 + r + 8)) * NBLK + blockIdx.x] = make_float2(m_hi[mi], l1);
        }
    }

    // write P'
#pragma unroll
    for (int mi = 0; mi < 2; mi++)
#pragma unroll
        for (int nj = 0; nj < 8; nj++) {
            float* cp = C + (long long)(wh + mi*16 + gid) * MAXS + t0 + wt + nj*8 + 2*tig;
            *(float2*)cp            = make_float2(acc[mi][nj][0], acc[mi][nj][1]);
            *(float2*)(cp + 8*MAXS) = make_float2(acc[mi][nj][2], acc[mi][nj][3]);
        }
}

// ---------------- combine weights ----------------
__global__ void __launch_bounds__(256) wcomb_kernel(
    const float2* __restrict__ mlv, float* __restrict__ wv)
{
    int row = blockIdx.x * 256 + threadIdx.x;
    if (row >= BATCH * H) return;
    const float2* p = mlv + (long long)row * NBLK;
    float2 v[NBLK];
    float M = -1e30f;
#pragma unroll
    for (int i = 0; i < NBLK; i++) { v[i] = p[i]; M = fmaxf(M, v[i].x); }
    float L = 0.f;
#pragma unroll
    for (int i = 0; i < NBLK; i++) L += __expf(v[i].x - M) * v[i].y;
    float inv = 1.f / L;
#pragma unroll
    for (int i = 0; i < NBLK; i++)
        wv[(long long)row * NBLK + i] = __expf(v[i].x - M) * inv;
}

// =====================================================================
// olat: tile 64h x 256c, split-k (8), cp.async 3-stage B ring (R14)
// =====================================================================
#define OL_SMEM 64000
__global__ void __launch_bounds__(256) olat_w(
    const float* __restrict__ P, const float* __restrict__ kvc,
    const float* __restrict__ kvnew, const float* __restrict__ wv,
    float* __restrict__ O, const int* __restrict__ spos_p)
{
    extern __shared__ char smraw[];
    unsigned (*As)[16][72] = (unsigned (*)[16][72])(smraw);
    float* Bsf            = (float*)(smraw + 9216);
    float (*ws)[16]       = (float (*)[16])(smraw + 9216 + 50688);

    const int b = blockIdx.z, spos = *spos_p;
    const int c0 = blockIdx.x * 256;
    const int hb = blockIdx.y >> 3, ks = blockIdx.y & 7;
    const int h0 = hb * 64;
    const float* A = P + ((long long)b * H + h0) * MAXS;
    float* C = O + ((long long)b * H + h0) * KVLR;

    const int tid = threadIdx.x, lane = tid & 31, wid = tid >> 5;
    const int gid = lane >> 2, tig = lane & 3;
    const int wh = (wid & 1) * 32, wc = (wid >> 1) * 64;

#pragma unroll
    for (int j = 0; j < 4; j++) {
        int idx = tid * 4 + j;
        int r = idx >> 4, blk = idx & 15;
        ws[r][blk] = wv[((long long)(b * H + h0 + r)) * NBLK + blk];
    }
    __syncthreads();

    const int ah = tid >> 2, akq = (tid & 3) * 4;
    const int acol = ah ^ (8 * ((akq >> 2) & 3));
    const int kbeg = ks * (MAXS/8);
    const int nIter = (MAXS/8) / 16;

    int brow_r[4], brow_c[4];
#pragma unroll
    for (int j = 0; j < 4; j++) {
        int idx = tid + j * 256;
        brow_r[j] = idx >> 6;
        brow_c[j] = (idx & 63) * 4;
    }
    const unsigned bsb = s2u(Bsf);

#pragma unroll
    for (int st = 0; st < 2; st++) {
        const int k0 = kbeg + st * 16;
#pragma unroll
        for (int j = 0; j < 4; j++) {
            int t = k0 + brow_r[j];
            const float* src = (t == spos) ? (kvnew + (long long)b * KVLR + c0 + brow_c[j])
                                           : (kvc + ((long long)b * MAXS + t) * KVLR + c0 + brow_c[j]);
            cpa16(bsb + (unsigned)(st * 16896 + (brow_r[j] * 264 + brow_c[j]) * 4), src);
        }
        CPA_COMMIT();
    }
    float4 ra;
    {
        float w0 = ws[ah][kbeg >> 8];
        ra = *(const float4*)(A + (long long)ah * MAXS + kbeg + akq);
        ra.x *= w0; ra.y *= w0; ra.z *= w0; ra.w *= w0;
    }
    As[0][akq+0][acol] = f2tf(ra.x); As[0][akq+1][acol] = f2tf(ra.y);
    As[0][akq+2][acol] = f2tf(ra.z); As[0][akq+3][acol] = f2tf(ra.w);

    float acc[2][8][4];
#pragma unroll
    for (int mi = 0; mi < 2; mi++)
#pragma unroll
        for (int nj = 0; nj < 8; nj++)
#pragma unroll
            for (int r = 0; r < 4; r++) acc[mi][nj][r] = 0.f;

    for (int it = 0; it < nIter; it++) {
        const int cur = it & 1, nxt = cur ^ 1;
        const bool more = (it + 1) < nIter;
        if (more) {
            const int k1 = kbeg + (it + 1) * 16;
            float w0 = ws[ah][k1 >> 8];
            ra = *(const float4*)(A + (long long)ah * MAXS + k1 + akq);
            ra.x *= w0; ra.y *= w0; ra.z *= w0; ra.w *= w0;
        }

        CPA_WAIT1();
        __syncthreads();

        if (it + 2 < nIter) {
            const int k0 = kbeg + (it + 2) * 16;
            const unsigned sb = bsb + (unsigned)(((it + 2) % 3) * 16896);
#pragma unroll
            for (int j = 0; j < 4; j++) {
                int t = k0 + brow_r[j];
                const float* src = (t == spos) ? (kvnew + (long long)b * KVLR + c0 + brow_c[j])
                                               : (kvc + ((long long)b * MAXS + t) * KVLR + c0 + brow_c[j]);
                cpa16(sb + (unsigned)((brow_r[j] * 264 + brow_c[j]) * 4), src);
            }
        }
        CPA_COMMIT();

        const float* bst = Bsf + (it % 3) * 4224;
#pragma unroll
        for (int s = 0; s < 2; s++) {
            const int kk = s * 8;
            const int key0 = 8 * ((kk >> 2) & 3);
            const int key1 = 8 * (((kk >> 2) + 1) & 3);
            unsigned af[2][4];
#pragma unroll
            for (int mi = 0; mi < 2; mi++) {
                int r0 = wh + mi*16 + gid;
                af[mi][0] = As[cur][kk+tig  ][ r0    ^ key0];
                af[mi][1] = As[cur][kk+tig  ][(r0+8) ^ key0];
                af[mi][2] = As[cur][kk+tig+4][ r0    ^ key1];
                af[mi][3] = As[cur][kk+tig+4][(r0+8) ^ key1];
            }
            unsigned bf[8][2];
#pragma unroll
            for (int nj = 0; nj < 8; nj++) {
                bf[nj][0] = f2tf(bst[(kk+tig  ) * 264 + wc + nj*8 + gid]);
                bf[nj][1] = f2tf(bst[(kk+tig+4) * 264 + wc + nj*8 + gid]);
            }
#pragma unroll
            for (int mi = 0; mi < 2; mi++)
#pragma unroll
                for (int nj = 0; nj < 8; nj++)
                    mma8(acc[mi][nj], af[mi], bf[nj]);
        }
        if (more) {
            As[nxt][akq+0][acol] = f2tf(ra.x); As[nxt][akq+1][acol] = f2tf(ra.y);
            As[nxt][akq+2][acol] = f2tf(ra.z); As[nxt][akq+3][acol] = f2tf(ra.w);
        }
    }

#pragma unroll
    for (int mi = 0; mi < 2; mi++)
#pragma unroll
        for (int nj = 0; nj < 8; nj++) {
            float* cp = C + (long long)(wh + mi*16 + gid) * KVLR + c0 + wc + nj*8 + 2*tig;
            atomicAdd(cp,            acc[mi][nj][0]);
            atomicAdd(cp + 1,        acc[mi][nj][1]);
            atomicAdd(cp + 8*KVLR,   acc[mi][nj][2]);
            atomicAdd(cp + 8*KVLR+1, acc[mi][nj][3]);
        }
}

// =====================================================================
// FFMA split-K GEMV (kvfull, ohead)
// =====================================================================
template<int BN, int TN>
__global__ void __launch_bounds__(256) gemv_splitk(
    const float* __restrict__ A, const float* __restrict__ B, float* __restrict__ C,
    int N, int lda, int ldb, int ldc, int kChunk,
    long long aB, long long bB, long long cB)
{
    A += (long long)blockIdx.z * aB;
    B += (long long)blockIdx.z * bB;
    C += (long long)blockIdx.z * cB;
    const int n0 = blockIdx.x * BN;
    const int ks = blockIdx.y * kChunk;
    const int ke = ks + kChunk;

    __shared__ __align__(16) ull   As2[16][32];
    __shared__ __align__(16) float Bsf2 [16][BN];

    const int tid = threadIdx.x;
    const int tx = tid & 31, ty = tid >> 5;

    const bool aon = tid < 128;
    const int am = tid >> 2, akq = (tid & 3) << 2;
    constexpr int PER = BN / 64;
    const int bn  = tid % BN;
    const int bkq = (tid / BN) * PER;
    const bool bon = (n0 + bn) < N;

    float4 ra = make_float4(0,0,0,0);
    float4 rb[PER];
#pragma unroll
    for (int j = 0; j < PER; j++) rb[j] = make_float4(0,0,0,0);

    if (aon) ra = *(const float4*)(A + (long long)am * lda + ks + akq);
    if (bon) {
        const float* bp = B + (long long)(n0 + bn) * ldb + ks + bkq * 4;
#pragma unroll
        for (int j = 0; j < PER; j++) rb[j] = *(const float4*)(bp + j * 4);
    }
    if (aon) {
        As2[akq+0][am] = dup2(ra.x); As2[akq+1][am] = dup2(ra.y);
        As2[akq+2][am] = dup2(ra.z); As2[akq+3][am] = dup2(ra.w);
    }
#pragma unroll
    for (int j = 0; j < PER; j++) {
        Bsf2[(bkq+j)*4+0][bn] = rb[j].x;
        Bsf2[(bkq+j)*4+1][bn] = rb[j].y;
        Bsf2[(bkq+j)*4+2][bn] = rb[j].z;
        Bsf2[(bkq+j)*4+3][bn] = rb[j].w;
    }
    __syncthreads();

    ull acc[4][TN/2];
#pragma unroll
    for (int m = 0; m < 4; m++)
#pragma unroll
        for (int j = 0; j < TN/2; j++) acc[m][j] = 0ull;

    for (int k0 = ks; k0 < ke; k0 += 16) {
        const bool more = (k0 + 16) < ke;
        if (more) {
            if (aon) ra = *(const float4*)(A + (long long)am * lda + (k0+16) + akq);
            if (bon) {
                const float* bp = B + (long long)(n0 + bn) * ldb + (k0+16) + bkq * 4;
#pragma unroll
                for (int j = 0; j < PER; j++) rb[j] = *(const float4*)(bp + j * 4);
            }
        }
#pragma unroll
        for (int kk = 0; kk < 16; kk++) {
            ulonglong2 a01 = *(const ulonglong2*)&As2[kk][ty*4];
            ulonglong2 a23 = *(const ulonglong2*)&As2[kk][ty*4+2];
            ull a[4] = {a01.x, a01.y, a23.x, a23.y};
            ull bq[TN/2];
            if constexpr (TN == 8) {
                ulonglong2 b0 = *(const ulonglong2*)&Bsf2[kk][tx*8];
                ulonglong2 b1 = *(const ulonglong2*)&Bsf2[kk][tx*8+4];
                bq[0]=b0.x; bq[1]=b0.y; bq[2]=b1.x; bq[3]=b1.y;
            } else {
                ulonglong2 b0 = *(const ulonglong2*)&Bsf2[kk][tx*4];
                bq[0]=b0.x; bq[1]=b0.y;
            }
#pragma unroll
            for (int m = 0; m < 4; m++)
#pragma unroll
                for (int j = 0; j < TN/2; j++)
                    acc[m][j] = fma2(a[m], bq[j], acc[m][j]);
        }
        __syncthreads();
        if (more) {
            if (aon) {
                As2[akq+0][am] = dup2(ra.x); As2[akq+1][am] = dup2(ra.y);
                As2[akq+2][am] = dup2(ra.z); As2[akq+3][am] = dup2(ra.w);
            }
#pragma unroll
            for (int j = 0; j < PER; j++) {
                Bsf2[(bkq+j)*4+0][bn] = rb[j].x;
                Bsf2[(bkq+j)*4+1][bn] = rb[j].y;
                Bsf2[(bkq+j)*4+2][bn] = rb[j].z;
                Bsf2[(bkq+j)*4+3][bn] = rb[j].w;
            }
        }
        __syncthreads();
    }

    const int nb = n0 + tx * TN;
#pragma unroll
    for (int m = 0; m < 4; m++) {
        float* cp = C + (long long)(ty*4+m) * ldc + nb;
#pragma unroll
        for (int j = 0; j < TN/2; j++) {
            float2 f = u2f(acc[m][j]);
            if (nb + 2*j     < N) atomicAdd(cp + 2*j,     f.x);
            if (nb + 2*j + 1 < N) atomicAdd(cp + 2*j + 1, f.y);
        }
    }
}

// ---------------- launch ----------------
extern "C" void kernel_launch(void* const* d_in, const int* in_sizes, int n_in,
                              void* d_out, int out_size)
{
    const float* x        = (const float*)d_in[0];
    const float* fc       = (const float*)d_in[1];
    const float* fs       = (const float*)d_in[2];
    const float* kvc      = (const float*)d_in[3];
    const float* pec      = (const float*)d_in[4];
    const float* wq_a     = (const float*)d_in[5];
    const float* q_norm_w = (const float*)d_in[6];
    const float* wq_b     = (const float*)d_in[7];
    const float* wkv_a    = (const float*)d_in[8];
    const float* kv_norm  = (const float*)d_in[9];
    const float* wkv_b    = (const float*)d_in[10];
    const float* wo       = (const float*)d_in[11];
    const int*   spos     = (const int*)d_in[12];
    float*       out      = (float*)d_out;

    float *qlat, *kvfull, *kvnew, *penew, *q, *qcat, *scores, *ml, *wv, *olat, *ohead;
    cudaGetSymbolAddress((void**)&qlat,   g_qlat);
    cudaGetSymbolAddress((void**)&kvfull, g_kvfull);
    cudaGetSymbolAddress((void**)&kvnew,  g_kvnew);
    cudaGetSymbolAddress((void**)&penew,  g_penew);
    cudaGetSymbolAddress((void**)&q,      g_q);
    cudaGetSymbolAddress((void**)&qcat,   g_qcat);
    cudaGetSymbolAddress((void**)&scores, g_scores);
    cudaGetSymbolAddress((void**)&ml,     g_ml);
    cudaGetSymbolAddress((void**)&wv,     g_w);
    cudaGetSymbolAddress((void**)&olat,   g_olat);
    cudaGetSymbolAddress((void**)&ohead,  g_ohead);

    cudaFuncSetAttribute(gemv_mma,  cudaFuncAttributeMaxDynamicSharedMemorySize, GV_SMEM);
    cudaFuncSetAttribute(scores_sm, cudaFuncAttributeMaxDynamicSharedMemorySize, SC_SMEM);
    cudaFuncSetAttribute(olat_w,    cudaFuncAttributeMaxDynamicSharedMemorySize, OL_SMEM);

    cudaMemsetAsync(qlat,   0, (size_t)BATCH * QLR  * 4);
    cudaMemsetAsync(kvfull, 0, (size_t)BATCH * KCAT * 4);
    cudaMemsetAsync(q,      0, (size_t)BATCH * QDIM * 4);
    cudaMemsetAsync(olat,   0, (size_t)BATCH * H * KVLR * 4);
    cudaMemsetAsync(ohead,  0, (size_t)BATCH * ODIM * 4);
    cudaMemsetAsync(out,    0, (size_t)out_size * 4);

    dim3 blk(256);

    // q_lat = x @ wq_a^T   (N=1536, K=7168): 192 blocks
    gemv_mma<<<dim3(6,32,1), blk, GV_SMEM>>>(x, wq_a, qlat, DIM, DIM, QLR, 224);
    // kv_full = x @ wkv_a^T (N=576, K=7168): 192 blocks
    gemv_splitk<256,8><<<dim3(3,64,1), blk>>>(x, wkv_a, kvfull, KCAT, DIM, DIM, KCAT, 112, 0,0,0);
    // merged rmsnorm(qlat) + kvprep
    norms_kernel<<<64, 256>>>(qlat, q_norm_w, kvfull, kv_norm, fc, fs, kvnew, penew);
    // q = q_lat @ wq_b^T   (N=24576, K=1536): 1152 blocks
    gemv_mma<<<dim3(96,12,1), blk, GV_SMEM>>>(qlat, wq_b, q, QLR, QLR, QDIM, 128);
    qrope_kernel<<<512, 256>>>(q, fc, fs, qcat);
    // q_abs: 256 blocks
    qabs_kernel<<<256, 256>>>(q, wkv_b, qcat);
    // scores + block-local softmax (cp.async pipeline)
    scores_sm<<<dim3(MAXS/256, H/64, BATCH), blk, SC_SMEM>>>(
        qcat, kvc, pec, kvnew, penew, scores, (float2*)ml, spos);
    // block weights
    wcomb_kernel<<<(BATCH*H + 255)/256, 256>>>((const float2*)ml, wv);
    // weighted olat (cp.async pipeline): 1024 blocks
    olat_w<<<dim3(KVLR/256, 16, BATCH), blk, OL_SMEM>>>(scores, kvc, kvnew, wv, olat, spos);
    // ohead per head, 2 k-splits: 256 blocks
    gemv_splitk<128,4><<<dim3(1,2,H), blk>>>(olat, wkv_b + 128*KVLR, ohead,
                                             DV, H*KVLR, KVLR, ODIM, 256,
                                             (long long)KVLR, (long long)256*KVLR, (long long)DV);
    // out = ohead @ wo^T   (N=7168, K=16384): 896 blocks
    gemv_mma<<<dim3(28,32,1), blk, GV_SMEM>>>(ohead, wo, out, ODIM, ODIM, DIM, 512);
}

// round 16
// speedup vs baseline: 1.0139x; 1.0139x over previous
#include <cuda_runtime.h>
#include <cuda_bf16.h>

// ---------------- problem constants ----------------
#define BATCH 32
#define DIM   7168
#define H     128
#define QLR   1536
#define KVLR  512
#define DN    128
#define DR    64
#define DV    128
#define QKD   192
#define MAXS  4096
#define QDIM  (H*QKD)      // 24576
#define KCAT  (KVLR+DR)    // 576
#define ODIM  (H*DV)       // 16384
#define NBLK  (MAXS/256)   // 16 t-blocks

#define SCALE_F 0.07216878364870322f
#define EPS_F   1e-6f

typedef unsigned long long ull;

// ---------------- helpers ----------------
__device__ __forceinline__ ull fma2(ull a, ull b, ull c) {
    ull d;
    asm("fma.rn.f32x2 %0, %1, %2, %3;" : "=l"(d) : "l"(a), "l"(b), "l"(c));
    return d;
}
__device__ __forceinline__ ull dup2(float x) {
    ull d;
    asm("mov.b64 %0, {%1, %1};" : "=l"(d) : "f"(x));
    return d;
}
__device__ __forceinline__ float2 u2f(ull v) {
    float2 f;
    f.x = __uint_as_float((unsigned)(v & 0xffffffffull));
    f.y = __uint_as_float((unsigned)(v >> 32));
    return f;
}
__device__ __forceinline__ unsigned f2tf(float f) {
    unsigned u; asm("cvt.rna.tf32.f32 %0, %1;" : "=r"(u) : "f"(f)); return u;
}
__device__ __forceinline__ unsigned s2u(const void* p) {
    unsigned a;
    asm("{ .reg .u64 t; cvta.to.shared.u64 t, %1; cvt.u32.u64 %0, t; }" : "=r"(a) : "l"(p));
    return a;
}
__device__ __forceinline__ void cpa16(unsigned dst, const void* src) {
    asm volatile("cp.async.cg.shared.global [%0], [%1], 16;" :: "r"(dst), "l"(src));
}
#define CPA_COMMIT() asm volatile("cp.async.commit_group;" ::: "memory")
#define CPA_WAIT1()  asm volatile("cp.async.wait_group 1;" ::: "memory")
__device__ __forceinline__ void mma8(float* c, const unsigned* a, const unsigned* b) {
    asm volatile("mma.sync.aligned.m16n8k8.row.col.f32.tf32.tf32.f32 "
                 "{%0,%1,%2,%3}, {%4,%5,%6,%7}, {%8,%9}, {%0,%1,%2,%3};"
                 : "+f"(c[0]), "+f"(c[1]), "+f"(c[2]), "+f"(c[3])
                 : "r"(a[0]), "r"(a[1]), "r"(a[2]), "r"(a[3]),
                   "r"(b[0]), "r"(b[1]));
}

// ---------------- scratch ----------------
__device__ __align__(16) float g_qlat  [BATCH * QLR];
__device__ __align__(16) float g_kvfull[BATCH * KCAT];
__device__ __align__(16) float g_kvnew [BATCH * KVLR];
__device__ __align__(16) float g_penew [BATCH * DR];
__device__ __align__(16) float g_q     [BATCH * QDIM];
__device__ __align__(16) float g_qcat  [BATCH * H * KCAT];
__device__ __align__(16) float g_scores[(long long)BATCH * H * MAXS];
__device__ __align__(16) float g_ml    [BATCH * H * NBLK * 2];
__device__ __align__(16) float g_w     [BATCH * H * NBLK];
__device__ __align__(16) float g_olat  [BATCH * H * KVLR];
__device__ __align__(16) float g_ohead [BATCH * ODIM];

// ---------------- reductions ----------------
__device__ __forceinline__ float warpSum(float v) {
#pragma unroll
    for (int o = 16; o; o >>= 1) v += __shfl_xor_sync(0xffffffffu, v, o);
    return v;
}
__device__ __forceinline__ float blockSum256(float v) {
    __shared__ float sm[8];
    int lane = threadIdx.x & 31, w = threadIdx.x >> 5;
    __syncthreads();
    v = warpSum(v);
    if (!lane) sm[w] = v;
    __syncthreads();
    float r = 0.f;
#pragma unroll
    for (int i = 0; i < 8; i++) r += sm[i];
    return r;
}

// =====================================================================
// TF32 MMA split-K GEMV v3 (R14 proven): B via quad-LDG.128,
// 2-deep register ring; A staged in XOR-swizzled smem.
// =====================================================================
__global__ void __launch_bounds__(256) gemv_mma(
    const float* __restrict__ A, const float* __restrict__ B, float* __restrict__ C,
    int lda, int ldb, int ldc, int kChunk)
{
    const int n0 = blockIdx.x * 256;
    const int ks = blockIdx.y * kChunk;
    const int nIter = kChunk / 16;

    __shared__ unsigned As[2][16][40];

    const int tid = threadIdx.x, lane = tid & 31, wid = tid >> 5;
    const int gid = lane >> 2, tig = lane & 3;
    const int wn = wid * 32;

    const bool aon = tid < 128;
    const int am = tid >> 2, akq = (tid & 3) * 4;
    const int acol = am ^ (8 * ((akq >> 2) & 3));

    const float* brow[4];
#pragma unroll
    for (int nj = 0; nj < 4; nj++)
        brow[nj] = B + (long long)(n0 + wn + nj*8 + gid) * ldb + ks + 4*tig;

    float4 ra = make_float4(0,0,0,0);
    if (aon) ra = *(const float4*)(A + (long long)am * lda + ks + akq);
    float4 bbuf[2][4];
#pragma unroll
    for (int nj = 0; nj < 4; nj++) bbuf[0][nj] = *(const float4*)(brow[nj]);
    if (nIter > 1) {
#pragma unroll
        for (int nj = 0; nj < 4; nj++) bbuf[1][nj] = *(const float4*)(brow[nj] + 16);
    }
    if (aon) {
        As[0][akq+0][acol] = f2tf(ra.x); As[0][akq+1][acol] = f2tf(ra.y);
        As[0][akq+2][acol] = f2tf(ra.z); As[0][akq+3][acol] = f2tf(ra.w);
    }
    __syncthreads();

    float acc[2][4][4];
#pragma unroll
    for (int mi = 0; mi < 2; mi++)
#pragma unroll
        for (int nj = 0; nj < 4; nj++)
#pragma unroll
            for (int r = 0; r < 4; r++) acc[mi][nj][r] = 0.f;

    const int key = 8 * tig;

    for (int it = 0; it < nIter; it++) {
        const int cur = it & 1, nxt = cur ^ 1;
        const bool more = (it + 1) < nIter;

        unsigned bf[4][4];
#pragma unroll
        for (int nj = 0; nj < 4; nj++) {
            float4 f = bbuf[cur][nj];
            bf[nj][0] = f2tf(f.x); bf[nj][1] = f2tf(f.y);
            bf[nj][2] = f2tf(f.z); bf[nj][3] = f2tf(f.w);
        }
        if (it + 2 < nIter) {
#pragma unroll
            for (int nj = 0; nj < 4; nj++)
                bbuf[cur][nj] = *(const float4*)(brow[nj] + (it+2)*16);
        }
        if (more && aon)
            ra = *(const float4*)(A + (long long)am * lda + ks + (it+1)*16 + akq);

#pragma unroll
        for (int s = 0; s < 2; s++) {
            const int r0r = 4*tig + 2*s;
            unsigned af[2][4];
#pragma unroll
            for (int mi = 0; mi < 2; mi++) {
                int r0 = mi*16 + gid;
                af[mi][0] = As[cur][r0r  ][ r0    ^ key];
                af[mi][1] = As[cur][r0r  ][(r0+8) ^ key];
                af[mi][2] = As[cur][r0r+1][ r0    ^ key];
                af[mi][3] = As[cur][r0r+1][(r0+8) ^ key];
            }
#pragma unroll
            for (int mi = 0; mi < 2; mi++)
#pragma unroll
                for (int nj = 0; nj < 4; nj++)
                    mma8(acc[mi][nj], af[mi], &bf[nj][2*s]);
        }
        if (more && aon) {
            As[nxt][akq+0][acol] = f2tf(ra.x); As[nxt][akq+1][acol] = f2tf(ra.y);
            As[nxt][akq+2][acol] = f2tf(ra.z); As[nxt][akq+3][acol] = f2tf(ra.w);
        }
        __syncthreads();
    }

#pragma unroll
    for (int mi = 0; mi < 2; mi++)
#pragma unroll
        for (int nj = 0; nj < 4; nj++) {
            float* cp = C + (long long)(mi*16+gid)*ldc + n0 + wn + nj*8 + 2*tig;
            atomicAdd(cp,           acc[mi][nj][0]);
            atomicAdd(cp + 1,       acc[mi][nj][1]);
            atomicAdd(cp + 8*ldc,   acc[mi][nj][2]);
            atomicAdd(cp + 8*ldc+1, acc[mi][nj][3]);
        }
}

// ---------------- merged norms ----------------
__global__ void __launch_bounds__(256) norms_kernel(
    float* __restrict__ qlat, const float* __restrict__ q_norm_w,
    const float* __restrict__ kvfull, const float* __restrict__ kv_norm,
    const float* __restrict__ fc, const float* __restrict__ fs,
    float* __restrict__ kvnew, float* __restrict__ penew)
{
    if (blockIdx.x < 32) {
        int b = blockIdx.x;
        float* row = qlat + (long long)b * QLR;
        float ss = 0.f;
        for (int i = threadIdx.x; i < QLR; i += 256) { float x = row[i]; ss += x * x; }
        ss = blockSum256(ss);
        __shared__ float s_scale;
        if (threadIdx.x == 0) s_scale = rsqrtf(ss / (float)QLR + EPS_F);
        __syncthreads();
        float sc = s_scale;
        for (int i = threadIdx.x; i < QLR; i += 256) row[i] = row[i] * sc * q_norm_w[i];
    } else {
        int b = blockIdx.x - 32;
        const float* row = kvfull + (long long)b * KCAT;
        float ss = 0.f;
        for (int i = threadIdx.x; i < KVLR; i += 256) { float x = row[i]; ss += x * x; }
        ss = blockSum256(ss);
        __shared__ float s_scale;
        if (threadIdx.x == 0) s_scale = rsqrtf(ss / (float)KVLR + EPS_F);
        __syncthreads();
        float sc = s_scale;
        for (int i = threadIdx.x; i < KVLR; i += 256)
            kvnew[(long long)b * KVLR + i] = row[i] * sc * kv_norm[i];
        if (threadIdx.x < 32) {
            int i = threadIdx.x;
            float x1 = row[KVLR + 2 * i], x2 = row[KVLR + 2 * i + 1];
            float c = fc[i], s = fs[i];
            penew[(long long)b * DR + 2 * i]     = x1 * c - x2 * s;
            penew[(long long)b * DR + 2 * i + 1] = x1 * s + x2 * c;
        }
    }
}

// ---------------- q_abs (FFMA) + fused q-rope, 256 blocks ----------------
__global__ void __launch_bounds__(256) qabs_kernel(
    const float* __restrict__ q, const float* __restrict__ wkvb,
    const float* __restrict__ fc, const float* __restrict__ fs,
    float* __restrict__ qcat)
{
    int h = blockIdx.x >> 1;
    int half = blockIdx.x & 1;
    int c = half * 256 + threadIdx.x;
    __shared__ __align__(16) float sq[DN][BATCH];
    int tid = threadIdx.x;
#pragma unroll
    for (int i = 0; i < 16; i++) {
        int idx = tid + i * 256;
        int d = idx >> 5, b = idx & 31;
        sq[d][b] = q[(long long)b * QDIM + h * QKD + d];
    }
    // fused rope for this head (odd-half blocks): 32 b x 32 pairs
    if (half) {
#pragma unroll
        for (int j = 0; j < 4; j++) {
            int idx = tid + j * 256;
            int b = idx >> 5, i = idx & 31;
            const float* src = q + (long long)b * QDIM + h * QKD + DN;
            float x1 = src[2 * i], x2 = src[2 * i + 1];
            float cc = fc[i], ss = fs[i];
            float* dst = qcat + ((long long)b * H + h) * KCAT + KVLR;
            dst[2 * i]     = (x1 * cc - x2 * ss) * SCALE_F;
            dst[2 * i + 1] = (x1 * ss + x2 * cc) * SCALE_F;
        }
    }
    __syncthreads();
    ull acc[16];
#pragma unroll
    for (int i = 0; i < 16; i++) acc[i] = 0ull;
    const float* w = wkvb + (long long)h * 256 * KVLR + c;
#pragma unroll 4
    for (int d = 0; d < DN; d++) {
        ull w2 = dup2(w[(long long)d * KVLR]);
#pragma unroll
        for (int bp = 0; bp < 16; bp++) {
            ull qp = *(const ull*)&sq[d][bp * 2];
            acc[bp] = fma2(qp, w2, acc[bp]);
        }
    }
#pragma unroll
    for (int bp = 0; bp < 16; bp++) {
        float2 f = u2f(acc[bp]);
        qcat[((long long)(2 * bp + 0) * H + h) * KCAT + c] = f.x * SCALE_F;
        qcat[((long long)(2 * bp + 1) * H + h) * KCAT + c] = f.y * SCALE_F;
    }
}

// =====================================================================
// scores + block-local softmax, cp.async 3-stage B ring (R14 proven)
// =====================================================================
#define SC_SMEM 71680
__global__ void __launch_bounds__(256) scores_sm(
    const float* __restrict__ qcat, const float* __restrict__ kvc, const float* __restrict__ pec,
    const float* __restrict__ kvnew, const float* __restrict__ penew,
    float* __restrict__ S, float2* __restrict__ mlv, const int* __restrict__ spos_p)
{
    extern __shared__ char smraw[];
    unsigned (*As)[16][72] = (unsigned (*)[16][72])(smraw);
    float* Bsf            = (float*)(smraw + 9216);
    float (*red)[4]       = (float (*)[4])(smraw + 9216 + 61440);

    const int b = blockIdx.z, spos = *spos_p;
    const int t0 = blockIdx.x * 256, h0 = blockIdx.y * 64;
    const float* A = qcat + ((long long)b * H + h0) * KCAT;
    float* C = S + ((long long)b * H + h0) * MAXS;

    const int tid = threadIdx.x, lane = tid & 31, wid = tid >> 5;
    const int gid = lane >> 2, tig = lane & 3;
    const int wh = (wid & 1) * 32, wt = (wid >> 1) * 64;
    const int wtq = wid >> 1;

    const int ah = tid >> 2, akq = (tid & 3) * 4;
    const int acol = ah ^ (8 * ((akq >> 2) & 3));

    const int bt = t0 + tid;
    const float* kvsrc = (bt == spos) ? (kvnew + (long long)b * KVLR)
                                      : (kvc + ((long long)b * MAXS + bt) * KVLR);
    const float* pesrc = (bt == spos) ? (penew + (long long)b * DR)
                                      : (pec + ((long long)b * MAXS + bt) * DR);
    const unsigned browu = s2u(Bsf) + tid * 80;

    {
        unsigned d0 = browu;
        cpa16(d0, kvsrc);      cpa16(d0+16, kvsrc+4);
        cpa16(d0+32, kvsrc+8); cpa16(d0+48, kvsrc+12);
        CPA_COMMIT();
        unsigned d1 = browu + 20480;
        const float* s1 = kvsrc + 16;
        cpa16(d1, s1);      cpa16(d1+16, s1+4);
        cpa16(d1+32, s1+8); cpa16(d1+48, s1+12);
        CPA_COMMIT();
    }
    float4 ra = *(const float4*)(A + (long long)ah * KCAT + akq);
    As[0][akq+0][acol] = f2tf(ra.x); As[0][akq+1][acol] = f2tf(ra.y);
    As[0][akq+2][acol] = f2tf(ra.z); As[0][akq+3][acol] = f2tf(ra.w);

    float acc[2][8][4];
#pragma unroll
    for (int mi = 0; mi < 2; mi++)
#pragma unroll
        for (int nj = 0; nj < 8; nj++)
#pragma unroll
            for (int r = 0; r < 4; r++) acc[mi][nj][r] = 0.f;

    for (int it = 0; it < KCAT / 16; it++) {
        const int cur = it & 1, nxt = cur ^ 1;
        const bool more = (it + 1) < KCAT / 16;
        if (more)
            ra = *(const float4*)(A + (long long)ah * KCAT + (it+1)*16 + akq);

        CPA_WAIT1();
        __syncthreads();

        if (it + 2 < KCAT / 16) {
            const int k0 = (it + 2) * 16;
            const float* src = (k0 < KVLR) ? (kvsrc + k0) : (pesrc + (k0 - KVLR));
            unsigned dst = browu + ((it + 2) % 3) * 20480;
            cpa16(dst, src);      cpa16(dst+16, src+4);
            cpa16(dst+32, src+8); cpa16(dst+48, src+12);
        }
        CPA_COMMIT();

        const float* bst = Bsf + (it % 3) * 5120;
#pragma unroll
        for (int s = 0; s < 2; s++) {
            const int kk = s * 8;
            const int key0 = 8 * ((kk >> 2) & 3);
            const int key1 = 8 * (((kk >> 2) + 1) & 3);
            unsigned af[2][4];
#pragma unroll
            for (int mi = 0; mi < 2; mi++) {
                int r0 = wh + mi*16 + gid;
                af[mi][0] = As[cur][kk+tig  ][ r0    ^ key0];
                af[mi][1] = As[cur][kk+tig  ][(r0+8) ^ key0];
                af[mi][2] = As[cur][kk+tig+4][ r0    ^ key1];
                af[mi][3] = As[cur][kk+tig+4][(r0+8) ^ key1];
            }
            unsigned bf[8][2];
#pragma unroll
            for (int nj = 0; nj < 8; nj++) {
                int row = (wt + nj*8 + gid) * 20;
                bf[nj][0] = f2tf(bst[row + kk + tig]);
                bf[nj][1] = f2tf(bst[row + kk + tig + 4]);
            }
#pragma unroll
            for (int mi = 0; mi < 2; mi++)
#pragma unroll
                for (int nj = 0; nj < 8; nj++)
                    mma8(acc[mi][nj], af[mi], bf[nj]);
        }
        if (more) {
            As[nxt][akq+0][acol] = f2tf(ra.x); As[nxt][akq+1][acol] = f2tf(ra.y);
            As[nxt][akq+2][acol] = f2tf(ra.z); As[nxt][akq+3][acol] = f2tf(ra.w);
        }
    }

    // ---------------- block-local softmax epilogue ----------------
    float m_lo[2], m_hi[2];
#pragma unroll
    for (int mi = 0; mi < 2; mi++) {
        float a = -1e30f, c = -1e30f;
#pragma unroll
        for (int nj = 0; nj < 8; nj++) {
            int t = t0 + wt + nj*8 + 2*tig;
            float v0 = (t     <= spos) ? acc[mi][nj][0] : -1e30f;
            float v1 = (t + 1 <= spos) ? acc[mi][nj][1] : -1e30f;
            float v2 = (t     <= spos) ? acc[mi][nj][2] : -1e30f;
            float v3 = (t + 1 <= spos) ? acc[mi][nj][3] : -1e30f;
            a = fmaxf(a, fmaxf(v0, v1));
            c = fmaxf(c, fmaxf(v2, v3));
        }
        a = fmaxf(a, __shfl_xor_sync(0xffffffffu, a, 1));
        a = fmaxf(a, __shfl_xor_sync(0xffffffffu, a, 2));
        c = fmaxf(c, __shfl_xor_sync(0xffffffffu, c, 1));
        c = fmaxf(c, __shfl_xor_sync(0xffffffffu, c, 2));
        m_lo[mi] = a; m_hi[mi] = c;
    }
    __syncthreads();
    if (tig == 0) {
#pragma unroll
        for (int mi = 0; mi < 2; mi++) {
            red[wh + mi*16 + gid    ][wtq] = m_lo[mi];
            red[wh + mi*16 + gid + 8][wtq] = m_hi[mi];
        }
    }
    __syncthreads();
#pragma unroll
    for (int mi = 0; mi < 2; mi++) {
        int r = wh + mi*16 + gid;
        m_lo[mi] = fmaxf(fmaxf(red[r][0],   red[r][1]),   fmaxf(red[r][2],   red[r][3]));
        m_hi[mi] = fmaxf(fmaxf(red[r+8][0], red[r+8][1]), fmaxf(red[r+8][2], red[r+8][3]));
    }
    __syncthreads();
    float s_lo[2] = {0.f, 0.f}, s_hi[2] = {0.f, 0.f};
#pragma unroll
    for (int mi = 0; mi < 2; mi++) {
#pragma unroll
        for (int nj = 0; nj < 8; nj++) {
            int t = t0 + wt + nj*8 + 2*tig;
            float e0 = (t     <= spos) ? __expf(acc[mi][nj][0] - m_lo[mi]) : 0.f;
            float e1 = (t + 1 <= spos) ? __expf(acc[mi][nj][1] - m_lo[mi]) : 0.f;
            float e2 = (t     <= spos) ? __expf(acc[mi][nj][2] - m_hi[mi]) : 0.f;
            float e3 = (t + 1 <= spos) ? __expf(acc[mi][nj][3] - m_hi[mi]) : 0.f;
            acc[mi][nj][0] = e0; acc[mi][nj][1] = e1;
            acc[mi][nj][2] = e2; acc[mi][nj][3] = e3;
            s_lo[mi] += e0 + e1; s_hi[mi] += e2 + e3;
        }
        s_lo[mi] += __shfl_xor_sync(0xffffffffu, s_lo[mi], 1);
        s_lo[mi] += __shfl_xor_sync(0xffffffffu, s_lo[mi], 2);
        s_hi[mi] += __shfl_xor_sync(0xffffffffu, s_hi[mi], 1);
        s_hi[mi] += __shfl_xor_sync(0xffffffffu, s_hi[mi], 2);
    }
    if (tig == 0) {
#pragma unroll
        for (int mi = 0; mi < 2; mi++) {
            red[wh + mi*16 + gid    ][wtq] = s_lo[mi];
            red[wh + mi*16 + gid + 8][wtq] = s_hi[mi];
        }
    }
    __syncthreads();
    if (wtq == 0 && tig == 0) {
#pragma unroll
        for (int mi = 0; mi < 2; mi++) {
            int r = wh + mi*16 + gid;
            float l0 = red[r][0]   + red[r][1]   + red[r][2]   + red[r][3];
            float l1 = red[r+8][0] + red[r+8][1] + red[r+8][2] + red[r+8][3];
            mlv[((long long)(b * H + h0 + r))     * NBLK + blockIdx.x] = make_float2(m_lo[mi], l0);
            mlv[((long long)(b * H + h0 + r + 8)) * NBLK + blockIdx.x] = make_float2(m_hi[mi], l1);
        }
    }

    // write P'
#pragma unroll
    for (int mi = 0; mi < 2; mi++)
#pragma unroll
        for (int nj = 0; nj < 8; nj++) {
            float* cp = C + (long long)(wh + mi*16 + gid) * MAXS + t0 + wt + nj*8 + 2*tig;
            *(float2*)cp            = make_float2(acc[mi][nj][0], acc[mi][nj][1]);
            *(float2*)(cp + 8*MAXS) = make_float2(acc[mi][nj][2], acc[mi][nj][3]);
        }
}

// ---------------- combine weights ----------------
__global__ void __launch_bounds__(256) wcomb_kernel(
    const float2* __restrict__ mlv, float* __restrict__ wv)
{
    int row = blockIdx.x * 256 + threadIdx.x;
    if (row >= BATCH * H) return;
    const float2* p = mlv + (long long)row * NBLK;
    float2 v[NBLK];
    float M = -1e30f;
#pragma unroll
    for (int i = 0; i < NBLK; i++) { v[i] = p[i]; M = fmaxf(M, v[i].x); }
    float L = 0.f;
#pragma unroll
    for (int i = 0; i < NBLK; i++) L += __expf(v[i].x - M) * v[i].y;
    float inv = 1.f / L;
#pragma unroll
    for (int i = 0; i < NBLK; i++)
        wv[(long long)row * NBLK + i] = __expf(v[i].x - M) * inv;
}

// =====================================================================
// olat: tile 64h x 256c, split-k (8), cp.async 3-stage B ring (R14)
// =====================================================================
#define OL_SMEM 64000
__global__ void __launch_bounds__(256) olat_w(
    const float* __restrict__ P, const float* __restrict__ kvc,
    const float* __restrict__ kvnew, const float* __restrict__ wv,
    float* __restrict__ O, const int* __restrict__ spos_p)
{
    extern __shared__ char smraw[];
    unsigned (*As)[16][72] = (unsigned (*)[16][72])(smraw);
    float* Bsf            = (float*)(smraw + 9216);
    float (*ws)[16]       = (float (*)[16])(smraw + 9216 + 50688);

    const int b = blockIdx.z, spos = *spos_p;
    const int c0 = blockIdx.x * 256;
    const int hb = blockIdx.y >> 3, ks = blockIdx.y & 7;
    const int h0 = hb * 64;
    const float* A = P + ((long long)b * H + h0) * MAXS;
    float* C = O + ((long long)b * H + h0) * KVLR;

    const int tid = threadIdx.x, lane = tid & 31, wid = tid >> 5;
    const int gid = lane >> 2, tig = lane & 3;
    const int wh = (wid & 1) * 32, wc = (wid >> 1) * 64;

#pragma unroll
    for (int j = 0; j < 4; j++) {
        int idx = tid * 4 + j;
        int r = idx >> 4, blk = idx & 15;
        ws[r][blk] = wv[((long long)(b * H + h0 + r)) * NBLK + blk];
    }
    __syncthreads();

    const int ah = tid >> 2, akq = (tid & 3) * 4;
    const int acol = ah ^ (8 * ((akq >> 2) & 3));
    const int kbeg = ks * (MAXS/8);
    const int nIter = (MAXS/8) / 16;

    int brow_r[4], brow_c[4];
#pragma unroll
    for (int j = 0; j < 4; j++) {
        int idx = tid + j * 256;
        brow_r[j] = idx >> 6;
        brow_c[j] = (idx & 63) * 4;
    }
    const unsigned bsb = s2u(Bsf);

#pragma unroll
    for (int st = 0; st < 2; st++) {
        const int k0 = kbeg + st * 16;
#pragma unroll
        for (int j = 0; j < 4; j++) {
            int t = k0 + brow_r[j];
            const float* src = (t == spos) ? (kvnew + (long long)b * KVLR + c0 + brow_c[j])
                                           : (kvc + ((long long)b * MAXS + t) * KVLR + c0 + brow_c[j]);
            cpa16(bsb + (unsigned)(st * 16896 + (brow_r[j] * 264 + brow_c[j]) * 4), src);
        }
        CPA_COMMIT();
    }
    float4 ra;
    {
        float w0 = ws[ah][kbeg >> 8];
        ra = *(const float4*)(A + (long long)ah * MAXS + kbeg + akq);
        ra.x *= w0; ra.y *= w0; ra.z *= w0; ra.w *= w0;
    }
    As[0][akq+0][acol] = f2tf(ra.x); As[0][akq+1][acol] = f2tf(ra.y);
    As[0][akq+2][acol] = f2tf(ra.z); As[0][akq+3][acol] = f2tf(ra.w);

    float acc[2][8][4];
#pragma unroll
    for (int mi = 0; mi < 2; mi++)
#pragma unroll
        for (int nj = 0; nj < 8; nj++)
#pragma unroll
            for (int r = 0; r < 4; r++) acc[mi][nj][r] = 0.f;

    for (int it = 0; it < nIter; it++) {
        const int cur = it & 1, nxt = cur ^ 1;
        const bool more = (it + 1) < nIter;
        if (more) {
            const int k1 = kbeg + (it + 1) * 16;
            float w0 = ws[ah][k1 >> 8];
            ra = *(const float4*)(A + (long long)ah * MAXS + k1 + akq);
            ra.x *= w0; ra.y *= w0; ra.z *= w0; ra.w *= w0;
        }

        CPA_WAIT1();
        __syncthreads();

        if (it + 2 < nIter) {
            const int k0 = kbeg + (it + 2) * 16;
            const unsigned sb = bsb + (unsigned)(((it + 2) % 3) * 16896);
#pragma unroll
            for (int j = 0; j < 4; j++) {
                int t = k0 + brow_r[j];
                const float* src = (t == spos) ? (kvnew + (long long)b * KVLR + c0 + brow_c[j])
                                               : (kvc + ((long long)b * MAXS + t) * KVLR + c0 + brow_c[j]);
                cpa16(sb + (unsigned)((brow_r[j] * 264 + brow_c[j]) * 4), src);
            }
        }
        CPA_COMMIT();

        const float* bst = Bsf + (it % 3) * 4224;
#pragma unroll
        for (int s = 0; s < 2; s++) {
            const int kk = s * 8;
            const int key0 = 8 * ((kk >> 2) & 3);
            const int key1 = 8 * (((kk >> 2) + 1) & 3);
            unsigned af[2][4];
#pragma unroll
            for (int mi = 0; mi < 2; mi++) {
                int r0 = wh + mi*16 + gid;
                af[mi][0] = As[cur][kk+tig  ][ r0    ^ key0];
                af[mi][1] = As[cur][kk+tig  ][(r0+8) ^ key0];
                af[mi][2] = As[cur][kk+tig+4][ r0    ^ key1];
                af[mi][3] = As[cur][kk+tig+4][(r0+8) ^ key1];
            }
            unsigned bf[8][2];
#pragma unroll
            for (int nj = 0; nj < 8; nj++) {
                bf[nj][0] = f2tf(bst[(kk+tig  ) * 264 + wc + nj*8 + gid]);
                bf[nj][1] = f2tf(bst[(kk+tig+4) * 264 + wc + nj*8 + gid]);
            }
#pragma unroll
            for (int mi = 0; mi < 2; mi++)
#pragma unroll
                for (int nj = 0; nj < 8; nj++)
                    mma8(acc[mi][nj], af[mi], bf[nj]);
        }
        if (more) {
            As[nxt][akq+0][acol] = f2tf(ra.x); As[nxt][akq+1][acol] = f2tf(ra.y);
            As[nxt][akq+2][acol] = f2tf(ra.z); As[nxt][akq+3][acol] = f2tf(ra.w);
        }
    }

#pragma unroll
    for (int mi = 0; mi < 2; mi++)
#pragma unroll
        for (int nj = 0; nj < 8; nj++) {
            float* cp = C + (long long)(wh + mi*16 + gid) * KVLR + c0 + wc + nj*8 + 2*tig;
            atomicAdd(cp,            acc[mi][nj][0]);
            atomicAdd(cp + 1,        acc[mi][nj][1]);
            atomicAdd(cp + 8*KVLR,   acc[mi][nj][2]);
            atomicAdd(cp + 8*KVLR+1, acc[mi][nj][3]);
        }
}

// =====================================================================
// FFMA split-K GEMV (kvfull, ohead)
// =====================================================================
template<int BN, int TN>
__global__ void __launch_bounds__(256) gemv_splitk(
    const float* __restrict__ A, const float* __restrict__ B, float* __restrict__ C,
    int N, int lda, int ldb, int ldc, int kChunk,
    long long aB, long long bB, long long cB)
{
    A += (long long)blockIdx.z * aB;
    B += (long long)blockIdx.z * bB;
    C += (long long)blockIdx.z * cB;
    const int n0 = blockIdx.x * BN;
    const int ks = blockIdx.y * kChunk;
    const int ke = ks + kChunk;

    __shared__ __align__(16) ull   As2[16][32];
    __shared__ __align__(16) float Bsf2 [16][BN];

    const int tid = threadIdx.x;
    const int tx = tid & 31, ty = tid >> 5;

    const bool aon = tid < 128;
    const int am = tid >> 2, akq = (tid & 3) << 2;
    constexpr int PER = BN / 64;
    const int bn  = tid % BN;
    const int bkq = (tid / BN) * PER;
    const bool bon = (n0 + bn) < N;

    float4 ra = make_float4(0,0,0,0);
    float4 rb[PER];
#pragma unroll
    for (int j = 0; j < PER; j++) rb[j] = make_float4(0,0,0,0);

    if (aon) ra = *(const float4*)(A + (long long)am * lda + ks + akq);
    if (bon) {
        const float* bp = B + (long long)(n0 + bn) * ldb + ks + bkq * 4;
#pragma unroll
        for (int j = 0; j < PER; j++) rb[j] = *(const float4*)(bp + j * 4);
    }
    if (aon) {
        As2[akq+0][am] = dup2(ra.x); As2[akq+1][am] = dup2(ra.y);
        As2[akq+2][am] = dup2(ra.z); As2[akq+3][am] = dup2(ra.w);
    }
#pragma unroll
    for (int j = 0; j < PER; j++) {
        Bsf2[(bkq+j)*4+0][bn] = rb[j].x;
        Bsf2[(bkq+j)*4+1][bn] = rb[j].y;
        Bsf2[(bkq+j)*4+2][bn] = rb[j].z;
        Bsf2[(bkq+j)*4+3][bn] = rb[j].w;
    }
    __syncthreads();

    ull acc[4][TN/2];
#pragma unroll
    for (int m = 0; m < 4; m++)
#pragma unroll
        for (int j = 0; j < TN/2; j++) acc[m][j] = 0ull;

    for (int k0 = ks; k0 < ke; k0 += 16) {
        const bool more = (k0 + 16) < ke;
        if (more) {
            if (aon) ra = *(const float4*)(A + (long long)am * lda + (k0+16) + akq);
            if (bon) {
                const float* bp = B + (long long)(n0 + bn) * ldb + (k0+16) + bkq * 4;
#pragma unroll
                for (int j = 0; j < PER; j++) rb[j] = *(const float4*)(bp + j * 4);
            }
        }
#pragma unroll
        for (int kk = 0; kk < 16; kk++) {
            ulonglong2 a01 = *(const ulonglong2*)&As2[kk][ty*4];
            ulonglong2 a23 = *(const ulonglong2*)&As2[kk][ty*4+2];
            ull a[4] = {a01.x, a01.y, a23.x, a23.y};
            ull bq[TN/2];
            if constexpr (TN == 8) {
                ulonglong2 b0 = *(const ulonglong2*)&Bsf2[kk][tx*8];
                ulonglong2 b1 = *(const ulonglong2*)&Bsf2[kk][tx*8+4];
                bq[0]=b0.x; bq[1]=b0.y; bq[2]=b1.x; bq[3]=b1.y;
            } else {
                ulonglong2 b0 = *(const ulonglong2*)&Bsf2[kk][tx*4];
                bq[0]=b0.x; bq[1]=b0.y;
            }
#pragma unroll
            for (int m = 0; m < 4; m++)
#pragma unroll
                for (int j = 0; j < TN/2; j++)
                    acc[m][j] = fma2(a[m], bq[j], acc[m][j]);
        }
        __syncthreads();
        if (more) {
            if (aon) {
                As2[akq+0][am] = dup2(ra.x); As2[akq+1][am] = dup2(ra.y);
                As2[akq+2][am] = dup2(ra.z); As2[akq+3][am] = dup2(ra.w);
            }
#pragma unroll
            for (int j = 0; j < PER; j++) {
                Bsf2[(bkq+j)*4+0][bn] = rb[j].x;
                Bsf2[(bkq+j)*4+1][bn] = rb[j].y;
                Bsf2[(bkq+j)*4+2][bn] = rb[j].z;
                Bsf2[(bkq+j)*4+3][bn] = rb[j].w;
            }
        }
        __syncthreads();
    }

    const int nb = n0 + tx * TN;
#pragma unroll
    for (int m = 0; m < 4; m++) {
        float* cp = C + (long long)(ty*4+m) * ldc + nb;
#pragma unroll
        for (int j = 0; j < TN/2; j++) {
            float2 f = u2f(acc[m][j]);
            if (nb + 2*j     < N) atomicAdd(cp + 2*j,     f.x);
            if (nb + 2*j + 1 < N) atomicAdd(cp + 2*j + 1, f.y);
        }
    }
}

// ---------------- launch ----------------
extern "C" void kernel_launch(void* const* d_in, const int* in_sizes, int n_in,
                              void* d_out, int out_size)
{
    const float* x        = (const float*)d_in[0];
    const float* fc       = (const float*)d_in[1];
    const float* fs       = (const float*)d_in[2];
    const float* kvc      = (const float*)d_in[3];
    const float* pec      = (const float*)d_in[4];
    const float* wq_a     = (const float*)d_in[5];
    const float* q_norm_w = (const float*)d_in[6];
    const float* wq_b     = (const float*)d_in[7];
    const float* wkv_a    = (const float*)d_in[8];
    const float* kv_norm  = (const float*)d_in[9];
    const float* wkv_b    = (const float*)d_in[10];
    const float* wo       = (const float*)d_in[11];
    const int*   spos     = (const int*)d_in[12];
    float*       out      = (float*)d_out;

    float *qlat, *kvfull, *kvnew, *penew, *q, *qcat, *scores, *ml, *wv, *olat, *ohead;
    cudaGetSymbolAddress((void**)&qlat,   g_qlat);
    cudaGetSymbolAddress((void**)&kvfull, g_kvfull);
    cudaGetSymbolAddress((void**)&kvnew,  g_kvnew);
    cudaGetSymbolAddress((void**)&penew,  g_penew);
    cudaGetSymbolAddress((void**)&q,      g_q);
    cudaGetSymbolAddress((void**)&qcat,   g_qcat);
    cudaGetSymbolAddress((void**)&scores, g_scores);
    cudaGetSymbolAddress((void**)&ml,     g_ml);
    cudaGetSymbolAddress((void**)&wv,     g_w);
    cudaGetSymbolAddress((void**)&olat,   g_olat);
    cudaGetSymbolAddress((void**)&ohead,  g_ohead);

    cudaFuncSetAttribute(scores_sm, cudaFuncAttributeMaxDynamicSharedMemorySize, SC_SMEM);
    cudaFuncSetAttribute(olat_w,    cudaFuncAttributeMaxDynamicSharedMemorySize, OL_SMEM);

    cudaMemsetAsync(qlat,   0, (size_t)BATCH * QLR  * 4);
    cudaMemsetAsync(kvfull, 0, (size_t)BATCH * KCAT * 4);
    cudaMemsetAsync(q,      0, (size_t)BATCH * QDIM * 4);
    cudaMemsetAsync(olat,   0, (size_t)BATCH * H * KVLR * 4);
    cudaMemsetAsync(ohead,  0, (size_t)BATCH * ODIM * 4);
    cudaMemsetAsync(out,    0, (size_t)out_size * 4);

    dim3 blk(256);

    // q_lat = x @ wq_a^T   (N=1536, K=7168): 192 blocks
    gemv_mma<<<dim3(6,32,1), blk>>>(x, wq_a, qlat, DIM, DIM, QLR, 224);
    // kv_full = x @ wkv_a^T (N=576, K=7168): 192 blocks
    gemv_splitk<256,8><<<dim3(3,64,1), blk>>>(x, wkv_a, kvfull, KCAT, DIM, DIM, KCAT, 112, 0,0,0);
    // merged rmsnorm(qlat) + kvprep
    norms_kernel<<<64, 256>>>(qlat, q_norm_w, kvfull, kv_norm, fc, fs, kvnew, penew);
    // q = q_lat @ wq_b^T   (N=24576, K=1536): 1152 blocks
    gemv_mma<<<dim3(96,12,1), blk>>>(qlat, wq_b, q, QLR, QLR, QDIM, 128);
    // q_abs + fused q-rope: 256 blocks
    qabs_kernel<<<256, 256>>>(q, wkv_b, fc, fs, qcat);
    // scores + block-local softmax (cp.async pipeline)
    scores_sm<<<dim3(MAXS/256, H/64, BATCH), blk, SC_SMEM>>>(
        qcat, kvc, pec, kvnew, penew, scores, (float2*)ml, spos);
    // block weights
    wcomb_kernel<<<(BATCH*H + 255)/256, 256>>>((const float2*)ml, wv);
    // weighted olat (cp.async pipeline): 1024 blocks
    olat_w<<<dim3(KVLR/256, 16, BATCH), blk, OL_SMEM>>>(scores, kvc, kvnew, wv, olat, spos);
    // ohead per head, 2 k-splits: 256 blocks
    gemv_splitk<128,4><<<dim3(1,2,H), blk>>>(olat, wkv_b + 128*KVLR, ohead,
                                             DV, H*KVLR, KVLR, ODIM, 256,
                                             (long long)KVLR, (long long)256*KVLR, (long long)DV);
    // out = ohead @ wo^T   (N=7168, K=16384): 896 blocks
    gemv_mma<<<dim3(28,32,1), blk>>>(ohead, wo, out, ODIM, ODIM, DIM, 512);
}

// round 17
// speedup vs baseline: 1.0450x; 1.0307x over previous
#include <cuda_runtime.h>
#include <cuda_bf16.h>

// ---------------- problem constants ----------------
#define BATCH 32
#define DIM   7168
#define H     128
#define QLR   1536
#define KVLR  512
#define DN    128
#define DR    64
#define DV    128
#define QKD   192
#define MAXS  4096
#define QDIM  (H*QKD)      // 24576
#define KCAT  (KVLR+DR)    // 576
#define ODIM  (H*DV)       // 16384
#define NBLK  (MAXS/256)   // 16 t-blocks

#define SCALE_F 0.07216878364870322f
#define EPS_F   1e-6f

typedef unsigned long long ull;

// ---------------- helpers ----------------
__device__ __forceinline__ ull fma2(ull a, ull b, ull c) {
    ull d;
    asm("fma.rn.f32x2 %0, %1, %2, %3;" : "=l"(d) : "l"(a), "l"(b), "l"(c));
    return d;
}
__device__ __forceinline__ ull dup2(float x) {
    ull d;
    asm("mov.b64 %0, {%1, %1};" : "=l"(d) : "f"(x));
    return d;
}
__device__ __forceinline__ float2 u2f(ull v) {
    float2 f;
    f.x = __uint_as_float((unsigned)(v & 0xffffffffull));
    f.y = __uint_as_float((unsigned)(v >> 32));
    return f;
}
__device__ __forceinline__ unsigned f2tf(float f) {
    unsigned u; asm("cvt.rna.tf32.f32 %0, %1;" : "=r"(u) : "f"(f)); return u;
}
__device__ __forceinline__ unsigned s2u(const void* p) {
    unsigned a;
    asm("{ .reg .u64 t; cvta.to.shared.u64 t, %1; cvt.u32.u64 %0, t; }" : "=r"(a) : "l"(p));
    return a;
}
__device__ __forceinline__ void cpa16(unsigned dst, const void* src) {
    asm volatile("cp.async.cg.shared.global [%0], [%1], 16;" :: "r"(dst), "l"(src));
}
#define CPA_COMMIT() asm volatile("cp.async.commit_group;" ::: "memory")
#define CPA_WAIT1()  asm volatile("cp.async.wait_group 1;" ::: "memory")
__device__ __forceinline__ void mma8(float* c, const unsigned* a, const unsigned* b) {
    asm volatile("mma.sync.aligned.m16n8k8.row.col.f32.tf32.tf32.f32 "
                 "{%0,%1,%2,%3}, {%4,%5,%6,%7}, {%8,%9}, {%0,%1,%2,%3};"
                 : "+f"(c[0]), "+f"(c[1]), "+f"(c[2]), "+f"(c[3])
                 : "r"(a[0]), "r"(a[1]), "r"(a[2]), "r"(a[3]),
                   "r"(b[0]), "r"(b[1]));
}

// ---------------- scratch ----------------
__device__ __align__(16) float g_qlat  [BATCH * QLR];
__device__ __align__(16) float g_kvfull[BATCH * KCAT];
__device__ __align__(16) float g_kvnew [BATCH * KVLR];
__device__ __align__(16) float g_penew [BATCH * DR];
__device__ __align__(16) float g_q     [BATCH * QDIM];
__device__ __align__(16) float g_qcat  [BATCH * H * KCAT];
__device__ __align__(16) float g_scores[(long long)BATCH * H * MAXS];
__device__ __align__(16) float g_ml    [BATCH * H * NBLK * 2];
__device__ __align__(16) float g_olat  [BATCH * H * KVLR];
__device__ __align__(16) float g_ohead [BATCH * ODIM];

// ---------------- reductions ----------------
__device__ __forceinline__ float warpSum(float v) {
#pragma unroll
    for (int o = 16; o; o >>= 1) v += __shfl_xor_sync(0xffffffffu, v, o);
    return v;
}
__device__ __forceinline__ float blockSum256(float v) {
    __shared__ float sm[8];
    int lane = threadIdx.x & 31, w = threadIdx.x >> 5;
    __syncthreads();
    v = warpSum(v);
    if (!lane) sm[w] = v;
    __syncthreads();
    float r = 0.f;
#pragma unroll
    for (int i = 0; i < 8; i++) r += sm[i];
    return r;
}

// =====================================================================
// TF32 MMA split-K GEMV v3 (proven): B via quad-LDG.128,
// 2-deep register ring; A staged in XOR-swizzled smem.
// =====================================================================
__global__ void __launch_bounds__(256) gemv_mma(
    const float* __restrict__ A, const float* __restrict__ B, float* __restrict__ C,
    int lda, int ldb, int ldc, int kChunk)
{
    const int n0 = blockIdx.x * 256;
    const int ks = blockIdx.y * kChunk;
    const int nIter = kChunk / 16;

    __shared__ unsigned As[2][16][40];

    const int tid = threadIdx.x, lane = tid & 31, wid = tid >> 5;
    const int gid = lane >> 2, tig = lane & 3;
    const int wn = wid * 32;

    const bool aon = tid < 128;
    const int am = tid >> 2, akq = (tid & 3) * 4;
    const int acol = am ^ (8 * ((akq >> 2) & 3));

    const float* brow[4];
#pragma unroll
    for (int nj = 0; nj < 4; nj++)
        brow[nj] = B + (long long)(n0 + wn + nj*8 + gid) * ldb + ks + 4*tig;

    float4 ra = make_float4(0,0,0,0);
    if (aon) ra = *(const float4*)(A + (long long)am * lda + ks + akq);
    float4 bbuf[2][4];
#pragma unroll
    for (int nj = 0; nj < 4; nj++) bbuf[0][nj] = *(const float4*)(brow[nj]);
    if (nIter > 1) {
#pragma unroll
        for (int nj = 0; nj < 4; nj++) bbuf[1][nj] = *(const float4*)(brow[nj] + 16);
    }
    if (aon) {
        As[0][akq+0][acol] = f2tf(ra.x); As[0][akq+1][acol] = f2tf(ra.y);
        As[0][akq+2][acol] = f2tf(ra.z); As[0][akq+3][acol] = f2tf(ra.w);
    }
    __syncthreads();

    float acc[2][4][4];
#pragma unroll
    for (int mi = 0; mi < 2; mi++)
#pragma unroll
        for (int nj = 0; nj < 4; nj++)
#pragma unroll
            for (int r = 0; r < 4; r++) acc[mi][nj][r] = 0.f;

    const int key = 8 * tig;

    for (int it = 0; it < nIter; it++) {
        const int cur = it & 1, nxt = cur ^ 1;
        const bool more = (it + 1) < nIter;

        unsigned bf[4][4];
#pragma unroll
        for (int nj = 0; nj < 4; nj++) {
            float4 f = bbuf[cur][nj];
            bf[nj][0] = f2tf(f.x); bf[nj][1] = f2tf(f.y);
            bf[nj][2] = f2tf(f.z); bf[nj][3] = f2tf(f.w);
        }
        if (it + 2 < nIter) {
#pragma unroll
            for (int nj = 0; nj < 4; nj++)
                bbuf[cur][nj] = *(const float4*)(brow[nj] + (it+2)*16);
        }
        if (more && aon)
            ra = *(const float4*)(A + (long long)am * lda + ks + (it+1)*16 + akq);

#pragma unroll
        for (int s = 0; s < 2; s++) {
            const int r0r = 4*tig + 2*s;
            unsigned af[2][4];
#pragma unroll
            for (int mi = 0; mi < 2; mi++) {
                int r0 = mi*16 + gid;
                af[mi][0] = As[cur][r0r  ][ r0    ^ key];
                af[mi][1] = As[cur][r0r  ][(r0+8) ^ key];
                af[mi][2] = As[cur][r0r+1][ r0    ^ key];
                af[mi][3] = As[cur][r0r+1][(r0+8) ^ key];
            }
#pragma unroll
            for (int mi = 0; mi < 2; mi++)
#pragma unroll
                for (int nj = 0; nj < 4; nj++)
                    mma8(acc[mi][nj], af[mi], &bf[nj][2*s]);
        }
        if (more && aon) {
            As[nxt][akq+0][acol] = f2tf(ra.x); As[nxt][akq+1][acol] = f2tf(ra.y);
            As[nxt][akq+2][acol] = f2tf(ra.z); As[nxt][akq+3][acol] = f2tf(ra.w);
        }
        __syncthreads();
    }

#pragma unroll
    for (int mi = 0; mi < 2; mi++)
#pragma unroll
        for (int nj = 0; nj < 4; nj++) {
            float* cp = C + (long long)(mi*16+gid)*ldc + n0 + wn + nj*8 + 2*tig;
            atomicAdd(cp,           acc[mi][nj][0]);
            atomicAdd(cp + 1,       acc[mi][nj][1]);
            atomicAdd(cp + 8*ldc,   acc[mi][nj][2]);
            atomicAdd(cp + 8*ldc+1, acc[mi][nj][3]);
        }
}

// ---------------- merged norms ----------------
__global__ void __launch_bounds__(256) norms_kernel(
    float* __restrict__ qlat, const float* __restrict__ q_norm_w,
    const float* __restrict__ kvfull, const float* __restrict__ kv_norm,
    const float* __restrict__ fc, const float* __restrict__ fs,
    float* __restrict__ kvnew, float* __restrict__ penew)
{
    if (blockIdx.x < 32) {
        int b = blockIdx.x;
        float* row = qlat + (long long)b * QLR;
        float ss = 0.f;
        for (int i = threadIdx.x; i < QLR; i += 256) { float x = row[i]; ss += x * x; }
        ss = blockSum256(ss);
        __shared__ float s_scale;
        if (threadIdx.x == 0) s_scale = rsqrtf(ss / (float)QLR + EPS_F);
        __syncthreads();
        float sc = s_scale;
        for (int i = threadIdx.x; i < QLR; i += 256) row[i] = row[i] * sc * q_norm_w[i];
    } else {
        int b = blockIdx.x - 32;
        const float* row = kvfull + (long long)b * KCAT;
        float ss = 0.f;
        for (int i = threadIdx.x; i < KVLR; i += 256) { float x = row[i]; ss += x * x; }
        ss = blockSum256(ss);
        __shared__ float s_scale;
        if (threadIdx.x == 0) s_scale = rsqrtf(ss / (float)KVLR + EPS_F);
        __syncthreads();
        float sc = s_scale;
        for (int i = threadIdx.x; i < KVLR; i += 256)
            kvnew[(long long)b * KVLR + i] = row[i] * sc * kv_norm[i];
        if (threadIdx.x < 32) {
            int i = threadIdx.x;
            float x1 = row[KVLR + 2 * i], x2 = row[KVLR + 2 * i + 1];
            float c = fc[i], s = fs[i];
            penew[(long long)b * DR + 2 * i]     = x1 * c - x2 * s;
            penew[(long long)b * DR + 2 * i + 1] = x1 * s + x2 * c;
        }
    }
}

// ---------------- q_abs (FFMA) + fused q-rope, 256 blocks ----------------
__global__ void __launch_bounds__(256) qabs_kernel(
    const float* __restrict__ q, const float* __restrict__ wkvb,
    const float* __restrict__ fc, const float* __restrict__ fs,
    float* __restrict__ qcat)
{
    int h = blockIdx.x >> 1;
    int half = blockIdx.x & 1;
    int c = half * 256 + threadIdx.x;
    __shared__ __align__(16) float sq[DN][BATCH];
    int tid = threadIdx.x;
#pragma unroll
    for (int i = 0; i < 16; i++) {
        int idx = tid + i * 256;
        int d = idx >> 5, b = idx & 31;
        sq[d][b] = q[(long long)b * QDIM + h * QKD + d];
    }
    if (half) {
#pragma unroll
        for (int j = 0; j < 4; j++) {
            int idx = tid + j * 256;
            int b = idx >> 5, i = idx & 31;
            const float* src = q + (long long)b * QDIM + h * QKD + DN;
            float x1 = src[2 * i], x2 = src[2 * i + 1];
            float cc = fc[i], ss = fs[i];
            float* dst = qcat + ((long long)b * H + h) * KCAT + KVLR;
            dst[2 * i]     = (x1 * cc - x2 * ss) * SCALE_F;
            dst[2 * i + 1] = (x1 * ss + x2 * cc) * SCALE_F;
        }
    }
    __syncthreads();
    ull acc[16];
#pragma unroll
    for (int i = 0; i < 16; i++) acc[i] = 0ull;
    const float* w = wkvb + (long long)h * 256 * KVLR + c;
#pragma unroll 4
    for (int d = 0; d < DN; d++) {
        ull w2 = dup2(w[(long long)d * KVLR]);
#pragma unroll
        for (int bp = 0; bp < 16; bp++) {
            ull qp = *(const ull*)&sq[d][bp * 2];
            acc[bp] = fma2(qp, w2, acc[bp]);
        }
    }
#pragma unroll
    for (int bp = 0; bp < 16; bp++) {
        float2 f = u2f(acc[bp]);
        qcat[((long long)(2 * bp + 0) * H + h) * KCAT + c] = f.x * SCALE_F;
        qcat[((long long)(2 * bp + 1) * H + h) * KCAT + c] = f.y * SCALE_F;
    }
}

// =====================================================================
// scores + block-local softmax, cp.async 3-stage B ring (proven)
// =====================================================================
#define SC_SMEM 71680
__global__ void __launch_bounds__(256) scores_sm(
    const float* __restrict__ qcat, const float* __restrict__ kvc, const float* __restrict__ pec,
    const float* __restrict__ kvnew, const float* __restrict__ penew,
    float* __restrict__ S, float2* __restrict__ mlv, const int* __restrict__ spos_p)
{
    extern __shared__ char smraw[];
    unsigned (*As)[16][72] = (unsigned (*)[16][72])(smraw);
    float* Bsf            = (float*)(smraw + 9216);
    float (*red)[4]       = (float (*)[4])(smraw + 9216 + 61440);

    const int b = blockIdx.z, spos = *spos_p;
    const int t0 = blockIdx.x * 256, h0 = blockIdx.y * 64;
    const float* A = qcat + ((long long)b * H + h0) * KCAT;
    float* C = S + ((long long)b * H + h0) * MAXS;

    const int tid = threadIdx.x, lane = tid & 31, wid = tid >> 5;
    const int gid = lane >> 2, tig = lane & 3;
    const int wh = (wid & 1) * 32, wt = (wid >> 1) * 64;
    const int wtq = wid >> 1;

    const int ah = tid >> 2, akq = (tid & 3) * 4;
    const int acol = ah ^ (8 * ((akq >> 2) & 3));

    const int bt = t0 + tid;
    const float* kvsrc = (bt == spos) ? (kvnew + (long long)b * KVLR)
                                      : (kvc + ((long long)b * MAXS + bt) * KVLR);
    const float* pesrc = (bt == spos) ? (penew + (long long)b * DR)
                                      : (pec + ((long long)b * MAXS + bt) * DR);
    const unsigned browu = s2u(Bsf) + tid * 80;

    {
        unsigned d0 = browu;
        cpa16(d0, kvsrc);      cpa16(d0+16, kvsrc+4);
        cpa16(d0+32, kvsrc+8); cpa16(d0+48, kvsrc+12);
        CPA_COMMIT();
        unsigned d1 = browu + 20480;
        const float* s1 = kvsrc + 16;
        cpa16(d1, s1);      cpa16(d1+16, s1+4);
        cpa16(d1+32, s1+8); cpa16(d1+48, s1+12);
        CPA_COMMIT();
    }
    float4 ra = *(const float4*)(A + (long long)ah * KCAT + akq);
    As[0][akq+0][acol] = f2tf(ra.x); As[0][akq+1][acol] = f2tf(ra.y);
    As[0][akq+2][acol] = f2tf(ra.z); As[0][akq+3][acol] = f2tf(ra.w);

    float acc[2][8][4];
#pragma unroll
    for (int mi = 0; mi < 2; mi++)
#pragma unroll
        for (int nj = 0; nj < 8; nj++)
#pragma unroll
            for (int r = 0; r < 4; r++) acc[mi][nj][r] = 0.f;

    for (int it = 0; it < KCAT / 16; it++) {
        const int cur = it & 1, nxt = cur ^ 1;
        const bool more = (it + 1) < KCAT / 16;
        if (more)
            ra = *(const float4*)(A + (long long)ah * KCAT + (it+1)*16 + akq);

        CPA_WAIT1();
        __syncthreads();

        if (it + 2 < KCAT / 16) {
            const int k0 = (it + 2) * 16;
            const float* src = (k0 < KVLR) ? (kvsrc + k0) : (pesrc + (k0 - KVLR));
            unsigned dst = browu + ((it + 2) % 3) * 20480;
            cpa16(dst, src);      cpa16(dst+16, src+4);
            cpa16(dst+32, src+8); cpa16(dst+48, src+12);
        }
        CPA_COMMIT();

        const float* bst = Bsf + (it % 3) * 5120;
#pragma unroll
        for (int s = 0; s < 2; s++) {
            const int kk = s * 8;
            const int key0 = 8 * ((kk >> 2) & 3);
            const int key1 = 8 * (((kk >> 2) + 1) & 3);
            unsigned af[2][4];
#pragma unroll
            for (int mi = 0; mi < 2; mi++) {
                int r0 = wh + mi*16 + gid;
                af[mi][0] = As[cur][kk+tig  ][ r0    ^ key0];
                af[mi][1] = As[cur][kk+tig  ][(r0+8) ^ key0];
                af[mi][2] = As[cur][kk+tig+4][ r0    ^ key1];
                af[mi][3] = As[cur][kk+tig+4][(r0+8) ^ key1];
            }
            unsigned bf[8][2];
#pragma unroll
            for (int nj = 0; nj < 8; nj++) {
                int row = (wt + nj*8 + gid) * 20;
                bf[nj][0] = f2tf(bst[row + kk + tig]);
                bf[nj][1] = f2tf(bst[row + kk + tig + 4]);
            }
#pragma unroll
            for (int mi = 0; mi < 2; mi++)
#pragma unroll
                for (int nj = 0; nj < 8; nj++)
                    mma8(acc[mi][nj], af[mi], bf[nj]);
        }
        if (more) {
            As[nxt][akq+0][acol] = f2tf(ra.x); As[nxt][akq+1][acol] = f2tf(ra.y);
            As[nxt][akq+2][acol] = f2tf(ra.z); As[nxt][akq+3][acol] = f2tf(ra.w);
        }
    }

    // ---------------- block-local softmax epilogue ----------------
    float m_lo[2], m_hi[2];
#pragma unroll
    for (int mi = 0; mi < 2; mi++) {
        float a = -1e30f, c = -1e30f;
#pragma unroll
        for (int nj = 0; nj < 8; nj++) {
            int t = t0 + wt + nj*8 + 2*tig;
            float v0 = (t     <= spos) ? acc[mi][nj][0] : -1e30f;
            float v1 = (t + 1 <= spos) ? acc[mi][nj][1] : -1e30f;
            float v2 = (t     <= spos) ? acc[mi][nj][2] : -1e30f;
            float v3 = (t + 1 <= spos) ? acc[mi][nj][3] : -1e30f;
            a = fmaxf(a, fmaxf(v0, v1));
            c = fmaxf(c, fmaxf(v2, v3));
        }
        a = fmaxf(a, __shfl_xor_sync(0xffffffffu, a, 1));
        a = fmaxf(a, __shfl_xor_sync(0xffffffffu, a, 2));
        c = fmaxf(c, __shfl_xor_sync(0xffffffffu, c, 1));
        c = fmaxf(c, __shfl_xor_sync(0xffffffffu, c, 2));
        m_lo[mi] = a; m_hi[mi] = c;
    }
    __syncthreads();
    if (tig == 0) {
#pragma unroll
        for (int mi = 0; mi < 2; mi++) {
            red[wh + mi*16 + gid    ][wtq] = m_lo[mi];
            red[wh + mi*16 + gid + 8][wtq] = m_hi[mi];
        }
    }
    __syncthreads();
#pragma unroll
    for (int mi = 0; mi < 2; mi++) {
        int r = wh + mi*16 + gid;
        m_lo[mi] = fmaxf(fmaxf(red[r][0],   red[r][1]),   fmaxf(red[r][2],   red[r][3]));
        m_hi[mi] = fmaxf(fmaxf(red[r+8][0], red[r+8][1]), fmaxf(red[r+8][2], red[r+8][3]));
    }
    __syncthreads();
    float s_lo[2] = {0.f, 0.f}, s_hi[2] = {0.f, 0.f};
#pragma unroll
    for (int mi = 0; mi < 2; mi++) {
#pragma unroll
        for (int nj = 0; nj < 8; nj++) {
            int t = t0 + wt + nj*8 + 2*tig;
            float e0 = (t     <= spos) ? __expf(acc[mi][nj][0] - m_lo[mi]) : 0.f;
            float e1 = (t + 1 <= spos) ? __expf(acc[mi][nj][1] - m_lo[mi]) : 0.f;
            float e2 = (t     <= spos) ? __expf(acc[mi][nj][2] - m_hi[mi]) : 0.f;
            float e3 = (t + 1 <= spos) ? __expf(acc[mi][nj][3] - m_hi[mi]) : 0.f;
            acc[mi][nj][0] = e0; acc[mi][nj][1] = e1;
            acc[mi][nj][2] = e2; acc[mi][nj][3] = e3;
            s_lo[mi] += e0 + e1; s_hi[mi] += e2 + e3;
        }
        s_lo[mi] += __shfl_xor_sync(0xffffffffu, s_lo[mi], 1);
        s_lo[mi] += __shfl_xor_sync(0xffffffffu, s_lo[mi], 2);
        s_hi[mi] += __shfl_xor_sync(0xffffffffu, s_hi[mi], 1);
        s_hi[mi] += __shfl_xor_sync(0xffffffffu, s_hi[mi], 2);
    }
    if (tig == 0) {
#pragma unroll
        for (int mi = 0; mi < 2; mi++) {
            red[wh + mi*16 + gid    ][wtq] = s_lo[mi];
            red[wh + mi*16 + gid + 8][wtq] = s_hi[mi];
        }
    }
    __syncthreads();
    if (wtq == 0 && tig == 0) {
#pragma unroll
        for (int mi = 0; mi < 2; mi++) {
            int r = wh + mi*16 + gid;
            float l0 = red[r][0]   + red[r][1]   + red[r][2]   + red[r][3];
            float l1 = red[r+8][0] + red[r+8][1] + red[r+8][2] + red[r+8][3];
            mlv[((long long)(b * H + h0 + r))     * NBLK + blockIdx.x] = make_float2(m_lo[mi], l0);
            mlv[((long long)(b * H + h0 + r + 8)) * NBLK + blockIdx.x] = make_float2(m_hi[mi], l1);
        }
    }

    // write P'
#pragma unroll
    for (int mi = 0; mi < 2; mi++)
#pragma unroll
        for (int nj = 0; nj < 8; nj++) {
            float* cp = C + (long long)(wh + mi*16 + gid) * MAXS + t0 + wt + nj*8 + 2*tig;
            *(float2*)cp            = make_float2(acc[mi][nj][0], acc[mi][nj][1]);
            *(float2*)(cp + 8*MAXS) = make_float2(acc[mi][nj][2], acc[mi][nj][3]);
        }
}

// =====================================================================
// olat: tile 64h x 256c, split-k (8), cp.async 3-stage B ring,
// block weights computed INLINE from (m,l) (wcomb folded in).
// =====================================================================
#define OL_SMEM 64000
__global__ void __launch_bounds__(256) olat_w(
    const float* __restrict__ P, const float* __restrict__ kvc,
    const float* __restrict__ kvnew, const float2* __restrict__ mlv,
    float* __restrict__ O, const int* __restrict__ spos_p)
{
    extern __shared__ char smraw[];
    unsigned (*As)[16][72] = (unsigned (*)[16][72])(smraw);
    float* Bsf            = (float*)(smraw + 9216);
    float (*ws)[16]       = (float (*)[16])(smraw + 9216 + 50688);

    const int b = blockIdx.z, spos = *spos_p;
    const int c0 = blockIdx.x * 256;
    const int hb = blockIdx.y >> 3, ks = blockIdx.y & 7;
    const int h0 = hb * 64;
    const float* A = P + ((long long)b * H + h0) * MAXS;
    float* C = O + ((long long)b * H + h0) * KVLR;

    const int tid = threadIdx.x, lane = tid & 31, wid = tid >> 5;
    const int gid = lane >> 2, tig = lane & 3;
    const int wh = (wid & 1) * 32, wc = (wid >> 1) * 64;

    // inline block weights: 4 lanes per row, each handles 4 blocks
    {
        const int r = tid >> 2, sub = tid & 3;
        const float2* p = mlv + ((long long)(b * H + h0 + r)) * NBLK + sub * 4;
        float2 v[4];
        float mx = -1e30f;
#pragma unroll
        for (int j = 0; j < 4; j++) { v[j] = p[j]; mx = fmaxf(mx, v[j].x); }
        mx = fmaxf(mx, __shfl_xor_sync(0xffffffffu, mx, 1));
        mx = fmaxf(mx, __shfl_xor_sync(0xffffffffu, mx, 2));
        float Ls = 0.f;
#pragma unroll
        for (int j = 0; j < 4; j++) Ls += __expf(v[j].x - mx) * v[j].y;
        Ls += __shfl_xor_sync(0xffffffffu, Ls, 1);
        Ls += __shfl_xor_sync(0xffffffffu, Ls, 2);
        float inv = 1.f / Ls;
#pragma unroll
        for (int j = 0; j < 4; j++)
            ws[r][sub * 4 + j] = __expf(v[j].x - mx) * inv;
    }
    __syncthreads();

    const int ah = tid >> 2, akq = (tid & 3) * 4;
    const int acol = ah ^ (8 * ((akq >> 2) & 3));
    const int kbeg = ks * (MAXS/8);
    const int nIter = (MAXS/8) / 16;

    int brow_r[4], brow_c[4];
#pragma unroll
    for (int j = 0; j < 4; j++) {
        int idx = tid + j * 256;
        brow_r[j] = idx >> 6;
        brow_c[j] = (idx & 63) * 4;
    }
    const unsigned bsb = s2u(Bsf);

#pragma unroll
    for (int st = 0; st < 2; st++) {
        const int k0 = kbeg + st * 16;
#pragma unroll
        for (int j = 0; j < 4; j++) {
            int t = k0 + brow_r[j];
            const float* src = (t == spos) ? (kvnew + (long long)b * KVLR + c0 + brow_c[j])
                                           : (kvc + ((long long)b * MAXS + t) * KVLR + c0 + brow_c[j]);
            cpa16(bsb + (unsigned)(st * 16896 + (brow_r[j] * 264 + brow_c[j]) * 4), src);
        }
        CPA_COMMIT();
    }
    float4 ra;
    {
        float w0 = ws[ah][kbeg >> 8];
        ra = *(const float4*)(A + (long long)ah * MAXS + kbeg + akq);
        ra.x *= w0; ra.y *= w0; ra.z *= w0; ra.w *= w0;
    }
    As[0][akq+0][acol] = f2tf(ra.x); As[0][akq+1][acol] = f2tf(ra.y);
    As[0][akq+2][acol] = f2tf(ra.z); As[0][akq+3][acol] = f2tf(ra.w);

    float acc[2][8][4];
#pragma unroll
    for (int mi = 0; mi < 2; mi++)
#pragma unroll
        for (int nj = 0; nj < 8; nj++)
#pragma unroll
            for (int r = 0; r < 4; r++) acc[mi][nj][r] = 0.f;

    for (int it = 0; it < nIter; it++) {
        const int cur = it & 1, nxt = cur ^ 1;
        const bool more = (it + 1) < nIter;
        if (more) {
            const int k1 = kbeg + (it + 1) * 16;
            float w0 = ws[ah][k1 >> 8];
            ra = *(const float4*)(A + (long long)ah * MAXS + k1 + akq);
            ra.x *= w0; ra.y *= w0; ra.z *= w0; ra.w *= w0;
        }

        CPA_WAIT1();
        __syncthreads();

        if (it + 2 < nIter) {
            const int k0 = kbeg + (it + 2) * 16;
            const unsigned sb = bsb + (unsigned)(((it + 2) % 3) * 16896);
#pragma unroll
            for (int j = 0; j < 4; j++) {
                int t = k0 + brow_r[j];
                const float* src = (t == spos) ? (kvnew + (long long)b * KVLR + c0 + brow_c[j])
                                               : (kvc + ((long long)b * MAXS + t) * KVLR + c0 + brow_c[j]);
                cpa16(sb + (unsigned)((brow_r[j] * 264 + brow_c[j]) * 4), src);
            }
        }
        CPA_COMMIT();

        const float* bst = Bsf + (it % 3) * 4224;
#pragma unroll
        for (int s = 0; s < 2; s++) {
            const int kk = s * 8;
            const int key0 = 8 * ((kk >> 2) & 3);
            const int key1 = 8 * (((kk >> 2) + 1) & 3);
            unsigned af[2][4];
#pragma unroll
            for (int mi = 0; mi < 2; mi++) {
                int r0 = wh + mi*16 + gid;
                af[mi][0] = As[cur][kk+tig  ][ r0    ^ key0];
                af[mi][1] = As[cur][kk+tig  ][(r0+8) ^ key0];
                af[mi][2] = As[cur][kk+tig+4][ r0    ^ key1];
                af[mi][3] = As[cur][kk+tig+4][(r0+8) ^ key1];
            }
            unsigned bf[8][2];
#pragma unroll
            for (int nj = 0; nj < 8; nj++) {
                bf[nj][0] = f2tf(bst[(kk+tig  ) * 264 + wc + nj*8 + gid]);
                bf[nj][1] = f2tf(bst[(kk+tig+4) * 264 + wc + nj*8 + gid]);
            }
#pragma unroll
            for (int mi = 0; mi < 2; mi++)
#pragma unroll
                for (int nj = 0; nj < 8; nj++)
                    mma8(acc[mi][nj], af[mi], bf[nj]);
        }
        if (more) {
            As[nxt][akq+0][acol] = f2tf(ra.x); As[nxt][akq+1][acol] = f2tf(ra.y);
            As[nxt][akq+2][acol] = f2tf(ra.z); As[nxt][akq+3][acol] = f2tf(ra.w);
        }
    }

#pragma unroll
    for (int mi = 0; mi < 2; mi++)
#pragma unroll
        for (int nj = 0; nj < 8; nj++) {
            float* cp = C + (long long)(wh + mi*16 + gid) * KVLR + c0 + wc + nj*8 + 2*tig;
            atomicAdd(cp,            acc[mi][nj][0]);
            atomicAdd(cp + 1,        acc[mi][nj][1]);
            atomicAdd(cp + 8*KVLR,   acc[mi][nj][2]);
            atomicAdd(cp + 8*KVLR+1, acc[mi][nj][3]);
        }
}

// =====================================================================
// FFMA split-K GEMV (kvfull, ohead)
// =====================================================================
template<int BN, int TN>
__global__ void __launch_bounds__(256) gemv_splitk(
    const float* __restrict__ A, const float* __restrict__ B, float* __restrict__ C,
    int N, int lda, int ldb, int ldc, int kChunk,
    long long aB, long long bB, long long cB)
{
    A += (long long)blockIdx.z * aB;
    B += (long long)blockIdx.z * bB;
    C += (long long)blockIdx.z * cB;
    const int n0 = blockIdx.x * BN;
    const int ks = blockIdx.y * kChunk;
    const int ke = ks + kChunk;

    __shared__ __align__(16) ull   As2[16][32];
    __shared__ __align__(16) float Bsf2 [16][BN];

    const int tid = threadIdx.x;
    const int tx = tid & 31, ty = tid >> 5;

    const bool aon = tid < 128;
    const int am = tid >> 2, akq = (tid & 3) << 2;
    constexpr int PER = BN / 64;
    const int bn  = tid % BN;
    const int bkq = (tid / BN) * PER;
    const bool bon = (n0 + bn) < N;

    float4 ra = make_float4(0,0,0,0);
    float4 rb[PER];
#pragma unroll
    for (int j = 0; j < PER; j++) rb[j] = make_float4(0,0,0,0);

    if (aon) ra = *(const float4*)(A + (long long)am * lda + ks + akq);
    if (bon) {
        const float* bp = B + (long long)(n0 + bn) * ldb + ks + bkq * 4;
#pragma unroll
        for (int j = 0; j < PER; j++) rb[j] = *(const float4*)(bp + j * 4);
    }
    if (aon) {
        As2[akq+0][am] = dup2(ra.x); As2[akq+1][am] = dup2(ra.y);
        As2[akq+2][am] = dup2(ra.z); As2[akq+3][am] = dup2(ra.w);
    }
#pragma unroll
    for (int j = 0; j < PER; j++) {
        Bsf2[(bkq+j)*4+0][bn] = rb[j].x;
        Bsf2[(bkq+j)*4+1][bn] = rb[j].y;
        Bsf2[(bkq+j)*4+2][bn] = rb[j].z;
        Bsf2[(bkq+j)*4+3][bn] = rb[j].w;
    }
    __syncthreads();

    ull acc[4][TN/2];
#pragma unroll
    for (int m = 0; m < 4; m++)
#pragma unroll
        for (int j = 0; j < TN/2; j++) acc[m][j] = 0ull;

    for (int k0 = ks; k0 < ke; k0 += 16) {
        const bool more = (k0 + 16) < ke;
        if (more) {
            if (aon) ra = *(const float4*)(A + (long long)am * lda + (k0+16) + akq);
            if (bon) {
                const float* bp = B + (long long)(n0 + bn) * ldb + (k0+16) + bkq * 4;
#pragma unroll
                for (int j = 0; j < PER; j++) rb[j] = *(const float4*)(bp + j * 4);
            }
        }
#pragma unroll
        for (int kk = 0; kk < 16; kk++) {
            ulonglong2 a01 = *(const ulonglong2*)&As2[kk][ty*4];
            ulonglong2 a23 = *(const ulonglong2*)&As2[kk][ty*4+2];
            ull a[4] = {a01.x, a01.y, a23.x, a23.y};
            ull bq[TN/2];
            if constexpr (TN == 8) {
                ulonglong2 b0 = *(const ulonglong2*)&Bsf2[kk][tx*8];
                ulonglong2 b1 = *(const ulonglong2*)&Bsf2[kk][tx*8+4];
                bq[0]=b0.x; bq[1]=b0.y; bq[2]=b1.x; bq[3]=b1.y;
            } else {
                ulonglong2 b0 = *(const ulonglong2*)&Bsf2[kk][tx*4];
                bq[0]=b0.x; bq[1]=b0.y;
            }
#pragma unroll
            for (int m = 0; m < 4; m++)
#pragma unroll
                for (int j = 0; j < TN/2; j++)
                    acc[m][j] = fma2(a[m], bq[j], acc[m][j]);
        }
        __syncthreads();
        if (more) {
            if (aon) {
                As2[akq+0][am] = dup2(ra.x); As2[akq+1][am] = dup2(ra.y);
                As2[akq+2][am] = dup2(ra.z); As2[akq+3][am] = dup2(ra.w);
            }
#pragma unroll
            for (int j = 0; j < PER; j++) {
                Bsf2[(bkq+j)*4+0][bn] = rb[j].x;
                Bsf2[(bkq+j)*4+1][bn] = rb[j].y;
                Bsf2[(bkq+j)*4+2][bn] = rb[j].z;
                Bsf2[(bkq+j)*4+3][bn] = rb[j].w;
            }
        }
        __syncthreads();
    }

    const int nb = n0 + tx * TN;
#pragma unroll
    for (int m = 0; m < 4; m++) {
        float* cp = C + (long long)(ty*4+m) * ldc + nb;
#pragma unroll
        for (int j = 0; j < TN/2; j++) {
            float2 f = u2f(acc[m][j]);
            if (nb + 2*j     < N) atomicAdd(cp + 2*j,     f.x);
            if (nb + 2*j + 1 < N) atomicAdd(cp + 2*j + 1, f.y);
        }
    }
}

// ---------------- launch ----------------
extern "C" void kernel_launch(void* const* d_in, const int* in_sizes, int n_in,
                              void* d_out, int out_size)
{
    const float* x        = (const float*)d_in[0];
    const float* fc       = (const float*)d_in[1];
    const float* fs       = (const float*)d_in[2];
    const float* kvc      = (const float*)d_in[3];
    const float* pec      = (const float*)d_in[4];
    const float* wq_a     = (const float*)d_in[5];
    const float* q_norm_w = (const float*)d_in[6];
    const float* wq_b     = (const float*)d_in[7];
    const float* wkv_a    = (const float*)d_in[8];
    const float* kv_norm  = (const float*)d_in[9];
    const float* wkv_b    = (const float*)d_in[10];
    const float* wo       = (const float*)d_in[11];
    const int*   spos     = (const int*)d_in[12];
    float*       out      = (float*)d_out;

    float *qlat, *kvfull, *kvnew, *penew, *q, *qcat, *scores, *ml, *olat, *ohead;
    cudaGetSymbolAddress((void**)&qlat,   g_qlat);
    cudaGetSymbolAddress((void**)&kvfull, g_kvfull);
    cudaGetSymbolAddress((void**)&kvnew,  g_kvnew);
    cudaGetSymbolAddress((void**)&penew,  g_penew);
    cudaGetSymbolAddress((void**)&q,      g_q);
    cudaGetSymbolAddress((void**)&qcat,   g_qcat);
    cudaGetSymbolAddress((void**)&scores, g_scores);
    cudaGetSymbolAddress((void**)&ml,     g_ml);
    cudaGetSymbolAddress((void**)&olat,   g_olat);
    cudaGetSymbolAddress((void**)&ohead,  g_ohead);

    cudaFuncSetAttribute(scores_sm, cudaFuncAttributeMaxDynamicSharedMemorySize, SC_SMEM);
    cudaFuncSetAttribute(olat_w,    cudaFuncAttributeMaxDynamicSharedMemorySize, OL_SMEM);

    cudaMemsetAsync(qlat,   0, (size_t)BATCH * QLR  * 4);
    cudaMemsetAsync(kvfull, 0, (size_t)BATCH * KCAT * 4);
    cudaMemsetAsync(q,      0, (size_t)BATCH * QDIM * 4);
    cudaMemsetAsync(olat,   0, (size_t)BATCH * H * KVLR * 4);
    cudaMemsetAsync(ohead,  0, (size_t)BATCH * ODIM * 4);
    cudaMemsetAsync(out,    0, (size_t)out_size * 4);

    dim3 blk(256);

    // q_lat = x @ wq_a^T   (N=1536, K=7168): 192 blocks
    gemv_mma<<<dim3(6,32,1), blk>>>(x, wq_a, qlat, DIM, DIM, QLR, 224);
    // kv_full = x @ wkv_a^T (N=576, K=7168): 192 blocks
    gemv_splitk<256,8><<<dim3(3,64,1), blk>>>(x, wkv_a, kvfull, KCAT, DIM, DIM, KCAT, 112, 0,0,0);
    // merged rmsnorm(qlat) + kvprep
    norms_kernel<<<64, 256>>>(qlat, q_norm_w, kvfull, kv_norm, fc, fs, kvnew, penew);
    // q = q_lat @ wq_b^T   (N=24576, K=1536): 1152 blocks
    gemv_mma<<<dim3(96,12,1), blk>>>(qlat, wq_b, q, QLR, QLR, QDIM, 128);
    // q_abs + fused q-rope: 256 blocks
    qabs_kernel<<<256, 256>>>(q, wkv_b, fc, fs, qcat);
    // scores + block-local softmax (cp.async pipeline)
    scores_sm<<<dim3(MAXS/256, H/64, BATCH), blk, SC_SMEM>>>(
        qcat, kvc, pec, kvnew, penew, scores, (float2*)ml, spos);
    // weighted olat (cp.async pipeline, inline block weights): 1024 blocks
    olat_w<<<dim3(KVLR/256, 16, BATCH), blk, OL_SMEM>>>(
        scores, kvc, kvnew, (const float2*)ml, olat, spos);
    // ohead per head, 2 k-splits: 256 blocks
    gemv_splitk<128,4><<<dim3(1,2,H), blk>>>(olat, wkv_b + 128*KVLR, ohead,
                                             DV, H*KVLR, KVLR, ODIM, 256,
                                             (long long)KVLR, (long long)256*KVLR, (long long)DV);
    // out = ohead @ wo^T   (N=7168, K=16384): 896 blocks
    gemv_mma<<<dim3(28,32,1), blk>>>(ohead, wo, out, ODIM, ODIM, DIM, 512);
}